// round 5
// baseline (speedup 1.0000x reference)
#include <cuda_runtime.h>
#include <cuda_bf16.h>
#include <cstdint>

// Problem constants (fixed by setup_inputs)
#define BB 4
#define CC 128
#define HH 64
#define WW 64
#define OO 128
#define TT 9

// Sampling metadata: per (b,h) row: 9 taps x 64 pixels.
__device__ float4  g_wt[BB * HH * TT * WW];   // bilinear weights * mask (0 if invalid)
__device__ ushort4 g_offp[BB * HH * TT * WW]; // clamped flat offsets (y*64+x), 4 corners
// Pre-split, pre-swizzled bf16 weights: [18 chunks][hi 16KB | lo 16KB]
__device__ char g_wb[18 * 32768];

// ---------------------------------------------------------------------------
// helpers
// ---------------------------------------------------------------------------
__device__ __forceinline__ unsigned long long pack2(float a, float b) {
    unsigned long long r;
    asm("mov.b64 %0, {%1, %2};"
        : "=l"(r) : "r"(__float_as_uint(a)), "r"(__float_as_uint(b)));
    return r;
}
__device__ __forceinline__ void unpack2(unsigned long long v, float& a, float& b) {
    unsigned int lo, hi;
    asm("mov.b64 {%0, %1}, %2;" : "=r"(lo), "=r"(hi) : "l"(v));
    a = __uint_as_float(lo);
    b = __uint_as_float(hi);
}
__device__ __forceinline__ void fma2(unsigned long long& d,
                                     unsigned long long a,
                                     unsigned long long b) {
    asm("fma.rn.f32x2 %0, %1, %2, %0;" : "+l"(d) : "l"(a), "l"(b));
}
__device__ __forceinline__ uint32_t smem_u32(const void* p) {
    uint32_t a;
    asm("{ .reg .u64 t; cvta.to.shared.u64 t, %1; cvt.u32.u64 %0, t; }"
        : "=r"(a) : "l"(p));
    return a;
}
#define SWZ128(o) ((o) ^ (((o) >> 3) & 0x70))

__device__ __forceinline__ void ldsm_x4(uint32_t* r, uint32_t addr) {
    asm volatile("ldmatrix.sync.aligned.m8n8.x4.shared.b16 {%0,%1,%2,%3}, [%4];"
                 : "=r"(r[0]), "=r"(r[1]), "=r"(r[2]), "=r"(r[3]) : "r"(addr));
}
__device__ __forceinline__ void mma_bf16(float* c, const uint32_t* a,
                                         const uint32_t* b) {
    asm volatile("mma.sync.aligned.m16n8k16.row.col.f32.bf16.bf16.f32 "
                 "{%0,%1,%2,%3}, {%4,%5,%6,%7}, {%8,%9}, {%0,%1,%2,%3};"
                 : "+f"(c[0]), "+f"(c[1]), "+f"(c[2]), "+f"(c[3])
                 : "r"(a[0]), "r"(a[1]), "r"(a[2]), "r"(a[3]),
                   "r"(b[0]), "r"(b[1]));
}
__device__ __forceinline__ uint32_t bf16split_hi(float v0, float v1, uint32_t& lw) {
    __nv_bfloat16 h0 = __float2bfloat16(v0);
    __nv_bfloat16 h1 = __float2bfloat16(v1);
    __nv_bfloat16 l0 = __float2bfloat16(v0 - __bfloat162float(h0));
    __nv_bfloat16 l1 = __float2bfloat16(v1 - __bfloat162float(h1));
    lw = ((uint32_t)__bfloat16_as_ushort(l1) << 16) | __bfloat16_as_ushort(l0);
    return ((uint32_t)__bfloat16_as_ushort(h1) << 16) | __bfloat16_as_ushort(h0);
}
__device__ __forceinline__ void cp_async16(uint32_t smem_dst, const void* gsrc) {
    asm volatile("cp.async.cg.shared.global [%0], [%1], 16;"
                 :: "r"(smem_dst), "l"(gsrc) : "memory");
}
__device__ __forceinline__ void cp_commit() {
    asm volatile("cp.async.commit_group;" ::: "memory");
}
__device__ __forceinline__ void cp_wait0() {
    asm volatile("cp.async.wait_group 0;" ::: "memory");
}
__device__ __forceinline__ void bar_sync_n(int id) {
    asm volatile("bar.sync %0, 256;" :: "r"(id) : "memory");
}
__device__ __forceinline__ void bar_arrive_n(int id) {
    asm volatile("bar.arrive %0, 256;" :: "r"(id) : "memory");
}

// named barrier ids
#define BFULL0 1
#define BFULL1 2
#define BEMPTY0 3
#define BEMPTY1 4

// ============================================================================
// Kernel 0: split weights into bf16 hi/lo, pre-swizzled per-chunk tiles.
// ============================================================================
__global__ __launch_bounds__(256) void k0_split_weights(const float* __restrict__ wgt)
{
    int id = blockIdx.x * 256 + threadIdx.x;  // 73728 items
    int ch = id >> 12;
    int r = id & 4095;
    int o = r >> 5, kp = r & 31;
    float2 wv = *(const float2*)(wgt + o * 1152 + ch * 64 + kp * 2);
    uint32_t lw, hw = bf16split_hi(wv.x, wv.y, lw);
    uint32_t off = SWZ128((uint32_t)(o * 128 + kp * 4));
    *(uint32_t*)(g_wb + ch * 32768 + off) = hw;
    *(uint32_t*)(g_wb + ch * 32768 + 16384 + off) = lw;
}

// ============================================================================
// Kernel 1: 27-channel conv (18 offset + 9 mask) + bilinear sampling metadata.
// ============================================================================
__global__ __launch_bounds__(256) void k1_sample_meta(
    const float* __restrict__ x,
    const float* __restrict__ ow, const float* __restrict__ ob,
    const float* __restrict__ mw, const float* __restrict__ mb)
{
    extern __shared__ float sm1[];
    float* wsm = sm1;              // [1152][28]
    float* red = sm1 + 1152 * 28;  // [4][28][64]

    const int bh = blockIdx.x;
    const int b = bh >> 6, h = bh & 63;
    const int tid = threadIdx.x;
    const int w = tid & 63, cg = tid >> 6;

    for (int i = tid; i < 27 * 1152; i += 256) {
        int oc = i / 1152;
        int r = i - oc * 1152;
        float v = (oc < 18) ? ow[oc * 1152 + r] : mw[(oc - 18) * 1152 + r];
        wsm[r * 28 + oc] = v;
    }
    for (int i = tid; i < 1152; i += 256) wsm[i * 28 + 27] = 0.f;
    __syncthreads();

    unsigned long long acc2[14];
#pragma unroll
    for (int q = 0; q < 14; q++) acc2[q] = 0ull;

    const float* xb = x + b * CC * HH * WW;
    for (int c = cg * 32; c < cg * 32 + 32; c++) {
        const float* xp = xb + c * HH * WW;
#pragma unroll
        for (int kh = 0; kh < 3; kh++) {
            int yy = h + kh - 1;
            if ((unsigned)yy >= (unsigned)HH) continue;
#pragma unroll
            for (int kw = 0; kw < 3; kw++) {
                int xx = w + kw - 1;
                if ((unsigned)xx >= (unsigned)WW) continue;
                float xv = xp[yy * WW + xx];
                unsigned long long xv2 = pack2(xv, xv);
                const ulonglong2* wp =
                    (const ulonglong2*)&wsm[(c * 9 + kh * 3 + kw) * 28];
#pragma unroll
                for (int q = 0; q < 7; q++) {
                    ulonglong2 u = wp[q];
                    fma2(acc2[2 * q], xv2, u.x);
                    fma2(acc2[2 * q + 1], xv2, u.y);
                }
            }
        }
    }

#pragma unroll
    for (int q = 0; q < 14; q++) {
        float a, b2;
        unpack2(acc2[q], a, b2);
        red[(cg * 28 + 2 * q) * 64 + w] = a;
        red[(cg * 28 + 2 * q + 1) * 64 + w] = b2;
    }
    __syncthreads();

    for (int i = tid; i < TT * 64; i += 256) {
        int t = i >> 6, ww = i & 63;
        float s0 = 0.f, s1 = 0.f, s2 = 0.f;
#pragma unroll
        for (int g = 0; g < 4; g++) {
            s0 += red[(g * 28 + 2 * t) * 64 + ww];
            s1 += red[(g * 28 + 2 * t + 1) * 64 + ww];
            s2 += red[(g * 28 + 18 + t) * 64 + ww];
        }
        float offy = s0 + ob[2 * t];
        float offx = s1 + ob[2 * t + 1];
        float m = 1.f / (1.f + __expf(-(s2 + mb[t])));

        int ii = t / 3;
        int jj = t - ii * 3;
        float py = (float)(h - 1 + ii) + offy;
        float px = (float)(ww - 1 + jj) + offx;
        float fy = floorf(py), fx = floorf(px);
        float ly = py - fy, lx = px - fx;
        int y0 = (int)fy, x0 = (int)fx;
        float hy = 1.f - ly, hx = 1.f - lx;
        float w00 = hy * hx * m, w01 = hy * lx * m;
        float w10 = ly * hx * m, w11 = ly * lx * m;
        bool vy0 = (unsigned)y0 < 64u;
        bool vy1 = (unsigned)(y0 + 1) < 64u;
        bool vx0 = (unsigned)x0 < 64u;
        bool vx1 = (unsigned)(x0 + 1) < 64u;
        if (!(vy0 && vx0)) w00 = 0.f;
        if (!(vy0 && vx1)) w01 = 0.f;
        if (!(vy1 && vx0)) w10 = 0.f;
        if (!(vy1 && vx1)) w11 = 0.f;
        int y0a = min(max(y0, 0), 63), y1a = min(max(y0 + 1, 0), 63);
        int x0a = min(max(x0, 0), 63), x1a = min(max(x0 + 1, 0), 63);
        g_wt[bh * 576 + i] = make_float4(w00, w01, w10, w11);
        g_offp[bh * 576 + i] =
            make_ushort4((unsigned short)(y0a * 64 + x0a),
                         (unsigned short)(y0a * 64 + x1a),
                         (unsigned short)(y1a * 64 + x0a),
                         (unsigned short)(y1a * 64 + x1a));
    }
}

// ============================================================================
// Kernel 2: warp-specialized deformable GEMM.
// grid = 256 (one image row, M=64), block = 256.
//   warps 0-3: consumers (each M64 x N32, mma.sync bf16 3-pass split)
//   warps 4-7: producers (A gather/split -> smem, B via cp.async from g_wb)
// 2 stage buffers (48KB each: A_hi 8K | A_lo 8K | B_hi 16K | B_lo 16K),
// named-barrier full/empty ping-pong. 2 CTAs/SM.
// ============================================================================
#define SM_WT  98304    // float4[576]
#define SM_OFF 107520   // ushort4[576]
#define SM_SC  112128   // float[128]
#define SM_SH  112640   // float[128]
#define SM2_BYTES 113152

__device__ __forceinline__ void stage_A_128(
    char* buf, const float* __restrict__ xb,
    const float4* __restrict__ s_wt, const ushort4* __restrict__ s_off,
    int k0, int p)
{
    char* alo = buf + 8192;
#pragma unroll 4
    for (int it = 0; it < 16; it++) {
        int id = it * 128 + p;
        int m = (id & 7) | (((id >> 5) & 7) << 3);
        int kp = ((id >> 3) & 3) | ((id >> 8) << 2);
        int k = k0 + kp * 2;

        unsigned c0 = (unsigned)k / 9u;
        int t0 = k - c0 * 9;
        unsigned c1 = (unsigned)(k + 1) / 9u;
        int t1 = (k + 1) - c1 * 9;

        float4 w0 = s_wt[t0 * 64 + m];
        ushort4 o0 = s_off[t0 * 64 + m];
        const float* xp0 = xb + c0 * 4096;
        float v0 = w0.x * xp0[o0.x] + w0.y * xp0[o0.y]
                 + w0.z * xp0[o0.z] + w0.w * xp0[o0.w];

        float4 w1 = s_wt[t1 * 64 + m];
        ushort4 o1 = s_off[t1 * 64 + m];
        const float* xp1 = xb + c1 * 4096;
        float v1 = w1.x * xp1[o1.x] + w1.y * xp1[o1.y]
                 + w1.z * xp1[o1.z] + w1.w * xp1[o1.w];

        uint32_t lw, hw = bf16split_hi(v0, v1, lw);
        uint32_t off = SWZ128((uint32_t)(m * 128 + kp * 4));
        *(uint32_t*)(buf + off) = hw;
        *(uint32_t*)(alo + off) = lw;
    }
}

__global__ __launch_bounds__(256, 2) void k2_deform_mma(
    const float* __restrict__ x,
    const float* __restrict__ gamma, const float* __restrict__ beta,
    const float* __restrict__ mean, const float* __restrict__ var,
    float* __restrict__ out)
{
    extern __shared__ char sm[];
    const uint32_t sb = smem_u32(sm);
    const int tid = threadIdx.x;
    const int wid = tid >> 5, lid = tid & 31;
    const int blk = blockIdx.x;
    const int b = blk >> 6;
    const int h = blk & 63;

    float4* s_wt = (float4*)(sm + SM_WT);
    ushort4* s_off = (ushort4*)(sm + SM_OFF);
    float* s_sc = (float*)(sm + SM_SC);
    float* s_sh = (float*)(sm + SM_SH);

    const int mbase = (b * 64 + h) * 576;
    for (int i = tid; i < 576; i += 256) {
        s_wt[i] = g_wt[mbase + i];
        s_off[i] = g_offp[mbase + i];
    }
    if (tid < 128) {
        float sc = gamma[tid] * rsqrtf(var[tid] + 1e-5f);
        s_sc[tid] = sc;
        s_sh[tid] = beta[tid] - mean[tid] * sc;
    }
    const float* xb = x + b * CC * HH * WW;
    __syncthreads();

    if (wid >= 4) {
        // ---------------- producers ----------------
        const int p = tid - 128;
        for (int ch = 0; ch < 18; ch++) {
            const int bf = ch & 1;
            char* buf = sm + bf * 49152;
            if (ch >= 2) bar_sync_n(BEMPTY0 + bf);
            // B: 32KB (hi+lo) via cp.async, 16 x 16B per thread
            {
                uint32_t bsm = sb + bf * 49152 + 16384;
                const char* gsrc = g_wb + ch * 32768;
#pragma unroll 4
                for (int it = 0; it < 16; it++) {
                    int ln = it * 128 + p;
                    cp_async16(bsm + ln * 16, gsrc + ln * 16);
                }
                cp_commit();
            }
            stage_A_128(buf, xb, s_wt, s_off, ch * 64, p);
            cp_wait0();
            bar_arrive_n(BFULL0 + bf);
        }
        return;
    }

    // ---------------- consumers ----------------
    const int wN = wid * 32;
    const int a_row = lid & 15;
    const int a_col = (lid >> 4) * 8;
    const int b_row = (lid & 7) + ((lid >> 4) << 3);
    const int b_col = ((lid >> 3) & 1) * 8;

    float acc[4][4][4];
#pragma unroll
    for (int mt = 0; mt < 4; mt++)
#pragma unroll
        for (int nt = 0; nt < 4; nt++)
#pragma unroll
            for (int i = 0; i < 4; i++) acc[mt][nt][i] = 0.f;

    for (int ch = 0; ch < 18; ch++) {
        const int bf = ch & 1;
        const uint32_t baseA = sb + bf * 49152;
        bar_sync_n(BFULL0 + bf);

#pragma unroll
        for (int ks = 0; ks < 4; ks++) {
            uint32_t bhf[2][4], blf[2][4];
#pragma unroll
            for (int p2 = 0; p2 < 2; p2++) {
                uint32_t off = SWZ128((uint32_t)((wN + p2 * 16 + b_row) * 128 +
                                                 (ks * 16 + b_col) * 2));
                ldsm_x4(bhf[p2], baseA + 16384 + off);
                ldsm_x4(blf[p2], baseA + 32768 + off);
            }
#pragma unroll
            for (int mt = 0; mt < 4; mt++) {
                uint32_t ah[4], al[4];
                uint32_t off = SWZ128((uint32_t)((mt * 16 + a_row) * 128 +
                                                 (ks * 16 + a_col) * 2));
                ldsm_x4(ah, baseA + off);
                ldsm_x4(al, baseA + 8192 + off);
#pragma unroll
                for (int nt = 0; nt < 4; nt++) {
                    const uint32_t* bhp = &bhf[nt >> 1][(nt & 1) * 2];
                    const uint32_t* blp = &blf[nt >> 1][(nt & 1) * 2];
                    mma_bf16(acc[mt][nt], ah, bhp);
                    mma_bf16(acc[mt][nt], ah, blp);
                    mma_bf16(acc[mt][nt], al, bhp);
                }
            }
        }
        bar_arrive_n(BEMPTY0 + bf);
    }

    // epilogue: BN + SiLU + store
    const int g = lid >> 2, t2 = (lid & 3) * 2;
#pragma unroll
    for (int mt = 0; mt < 4; mt++) {
#pragma unroll
        for (int nt = 0; nt < 4; nt++) {
#pragma unroll
            for (int i = 0; i < 4; i++) {
                int m = mt * 16 + g + ((i >> 1) ? 8 : 0);
                int n = wN + nt * 8 + t2 + (i & 1);
                float v = acc[mt][nt][i] * s_sc[n] + s_sh[n];
                v = v / (1.f + __expf(-v));
                out[((b * OO + n) * HH + h) * WW + m] = v;
            }
        }
    }
}

extern "C" void kernel_launch(void* const* d_in, const int* in_sizes, int n_in,
                              void* d_out, int out_size)
{
    const float* x  = (const float*)d_in[0];
    const float* ow = (const float*)d_in[1];
    const float* ob = (const float*)d_in[2];
    const float* mw = (const float*)d_in[3];
    const float* mb = (const float*)d_in[4];
    const float* wg = (const float*)d_in[5];
    const float* gg = (const float*)d_in[6];
    const float* bt = (const float*)d_in[7];
    const float* mu = (const float*)d_in[8];
    const float* vr = (const float*)d_in[9];
    float* out = (float*)d_out;

    const int SM1 = (1152 * 28 + 4 * 28 * 64) * 4;  // 157,696 B
    cudaFuncSetAttribute(k1_sample_meta,
                         cudaFuncAttributeMaxDynamicSharedMemorySize, SM1);
    cudaFuncSetAttribute(k2_deform_mma,
                         cudaFuncAttributeMaxDynamicSharedMemorySize, SM2_BYTES);

    k0_split_weights<<<288, 256>>>(wg);
    k1_sample_meta<<<BB * HH, 256, SM1>>>(x, ow, ob, mw, mb);
    k2_deform_mma<<<BB * HH, 256, SM2_BYTES>>>(x, gg, bt, mu, vr, out);
}

// round 6
// speedup vs baseline: 1.4253x; 1.4253x over previous
#include <cuda_runtime.h>
#include <cuda_bf16.h>
#include <cstdint>

// Problem constants (fixed by setup_inputs)
#define BB 4
#define CC 128
#define HH 64
#define WW 64
#define OO 128
#define TT 9

// Sampling metadata: per (b,h) row: 9 taps x 64 pixels.
__device__ float4  g_wt[BB * HH * TT * WW];   // bilinear weights * mask (0 if invalid)
__device__ ushort4 g_offp[BB * HH * TT * WW]; // clamped flat offsets (y*64+x), 4 corners
// Pre-split, pre-swizzled bf16 weights: [18 chunks][hi 16KB | lo 16KB]
__device__ __align__(16) char g_wb[18 * 32768];
// Sampled A matrix, bf16 hi/lo, stored as per-(GEMM CTA g, chunk ch) SW128
// tiles of 128 m x 64 k (16KB each): offset (g*18+ch)*16384 + SWZ128(mloc*128+kp*4)
__device__ __align__(16) char g_Ahi[128 * 18 * 16384];
__device__ __align__(16) char g_Alo[128 * 18 * 16384];

// ---------------------------------------------------------------------------
// helpers
// ---------------------------------------------------------------------------
__device__ __forceinline__ unsigned long long pack2(float a, float b) {
    unsigned long long r;
    asm("mov.b64 %0, {%1, %2};"
        : "=l"(r) : "r"(__float_as_uint(a)), "r"(__float_as_uint(b)));
    return r;
}
__device__ __forceinline__ void unpack2(unsigned long long v, float& a, float& b) {
    unsigned int lo, hi;
    asm("mov.b64 {%0, %1}, %2;" : "=r"(lo), "=r"(hi) : "l"(v));
    a = __uint_as_float(lo);
    b = __uint_as_float(hi);
}
__device__ __forceinline__ void fma2(unsigned long long& d,
                                     unsigned long long a,
                                     unsigned long long b) {
    asm("fma.rn.f32x2 %0, %1, %2, %0;" : "+l"(d) : "l"(a), "l"(b));
}
__device__ __forceinline__ uint32_t smem_u32(const void* p) {
    uint32_t a;
    asm("{ .reg .u64 t; cvta.to.shared.u64 t, %1; cvt.u32.u64 %0, t; }"
        : "=r"(a) : "l"(p));
    return a;
}
#define SWZ128(o) ((o) ^ (((o) >> 3) & 0x70))

__device__ __forceinline__ void ldsm_x4(uint32_t* r, uint32_t addr) {
    asm volatile("ldmatrix.sync.aligned.m8n8.x4.shared.b16 {%0,%1,%2,%3}, [%4];"
                 : "=r"(r[0]), "=r"(r[1]), "=r"(r[2]), "=r"(r[3]) : "r"(addr));
}
__device__ __forceinline__ void mma_bf16(float* c, const uint32_t* a,
                                         const uint32_t* b) {
    asm volatile("mma.sync.aligned.m16n8k16.row.col.f32.bf16.bf16.f32 "
                 "{%0,%1,%2,%3}, {%4,%5,%6,%7}, {%8,%9}, {%0,%1,%2,%3};"
                 : "+f"(c[0]), "+f"(c[1]), "+f"(c[2]), "+f"(c[3])
                 : "r"(a[0]), "r"(a[1]), "r"(a[2]), "r"(a[3]),
                   "r"(b[0]), "r"(b[1]));
}
__device__ __forceinline__ uint32_t bf16split_hi(float v0, float v1, uint32_t& lw) {
    __nv_bfloat16 h0 = __float2bfloat16(v0);
    __nv_bfloat16 h1 = __float2bfloat16(v1);
    __nv_bfloat16 l0 = __float2bfloat16(v0 - __bfloat162float(h0));
    __nv_bfloat16 l1 = __float2bfloat16(v1 - __bfloat162float(h1));
    lw = ((uint32_t)__bfloat16_as_ushort(l1) << 16) | __bfloat16_as_ushort(l0);
    return ((uint32_t)__bfloat16_as_ushort(h1) << 16) | __bfloat16_as_ushort(h0);
}
__device__ __forceinline__ void cp_async16(uint32_t smem_dst, const void* gsrc) {
    asm volatile("cp.async.cg.shared.global [%0], [%1], 16;"
                 :: "r"(smem_dst), "l"(gsrc) : "memory");
}
__device__ __forceinline__ void cp_commit() {
    asm volatile("cp.async.commit_group;" ::: "memory");
}
__device__ __forceinline__ void cp_wait2() {
    asm volatile("cp.async.wait_group 2;" ::: "memory");
}

// ============================================================================
// Kernel 1: 27-channel conv (18 offset + 9 mask) + bilinear sampling metadata.
// (proven since R1; unchanged)
// ============================================================================
__global__ __launch_bounds__(256) void k1_sample_meta(
    const float* __restrict__ x,
    const float* __restrict__ ow, const float* __restrict__ ob,
    const float* __restrict__ mw, const float* __restrict__ mb)
{
    extern __shared__ float sm1[];
    float* wsm = sm1;              // [1152][28]
    float* red = sm1 + 1152 * 28;  // [4][28][64]

    const int bh = blockIdx.x;
    const int b = bh >> 6, h = bh & 63;
    const int tid = threadIdx.x;
    const int w = tid & 63, cg = tid >> 6;

    for (int i = tid; i < 27 * 1152; i += 256) {
        int oc = i / 1152;
        int r = i - oc * 1152;
        float v = (oc < 18) ? ow[oc * 1152 + r] : mw[(oc - 18) * 1152 + r];
        wsm[r * 28 + oc] = v;
    }
    for (int i = tid; i < 1152; i += 256) wsm[i * 28 + 27] = 0.f;
    __syncthreads();

    unsigned long long acc2[14];
#pragma unroll
    for (int q = 0; q < 14; q++) acc2[q] = 0ull;

    const float* xb = x + b * CC * HH * WW;
    for (int c = cg * 32; c < cg * 32 + 32; c++) {
        const float* xp = xb + c * HH * WW;
#pragma unroll
        for (int kh = 0; kh < 3; kh++) {
            int yy = h + kh - 1;
            if ((unsigned)yy >= (unsigned)HH) continue;
#pragma unroll
            for (int kw = 0; kw < 3; kw++) {
                int xx = w + kw - 1;
                if ((unsigned)xx >= (unsigned)WW) continue;
                float xv = xp[yy * WW + xx];
                unsigned long long xv2 = pack2(xv, xv);
                const ulonglong2* wp =
                    (const ulonglong2*)&wsm[(c * 9 + kh * 3 + kw) * 28];
#pragma unroll
                for (int q = 0; q < 7; q++) {
                    ulonglong2 u = wp[q];
                    fma2(acc2[2 * q], xv2, u.x);
                    fma2(acc2[2 * q + 1], xv2, u.y);
                }
            }
        }
    }

#pragma unroll
    for (int q = 0; q < 14; q++) {
        float a, b2;
        unpack2(acc2[q], a, b2);
        red[(cg * 28 + 2 * q) * 64 + w] = a;
        red[(cg * 28 + 2 * q + 1) * 64 + w] = b2;
    }
    __syncthreads();

    for (int i = tid; i < TT * 64; i += 256) {
        int t = i >> 6, ww = i & 63;
        float s0 = 0.f, s1 = 0.f, s2 = 0.f;
#pragma unroll
        for (int g = 0; g < 4; g++) {
            s0 += red[(g * 28 + 2 * t) * 64 + ww];
            s1 += red[(g * 28 + 2 * t + 1) * 64 + ww];
            s2 += red[(g * 28 + 18 + t) * 64 + ww];
        }
        float offy = s0 + ob[2 * t];
        float offx = s1 + ob[2 * t + 1];
        float m = 1.f / (1.f + __expf(-(s2 + mb[t])));

        int ii = t / 3;
        int jj = t - ii * 3;
        float py = (float)(h - 1 + ii) + offy;
        float px = (float)(ww - 1 + jj) + offx;
        float fy = floorf(py), fx = floorf(px);
        float ly = py - fy, lx = px - fx;
        int y0 = (int)fy, x0 = (int)fx;
        float hy = 1.f - ly, hx = 1.f - lx;
        float w00 = hy * hx * m, w01 = hy * lx * m;
        float w10 = ly * hx * m, w11 = ly * lx * m;
        bool vy0 = (unsigned)y0 < 64u;
        bool vy1 = (unsigned)(y0 + 1) < 64u;
        bool vx0 = (unsigned)x0 < 64u;
        bool vx1 = (unsigned)(x0 + 1) < 64u;
        if (!(vy0 && vx0)) w00 = 0.f;
        if (!(vy0 && vx1)) w01 = 0.f;
        if (!(vy1 && vx0)) w10 = 0.f;
        if (!(vy1 && vx1)) w11 = 0.f;
        int y0a = min(max(y0, 0), 63), y1a = min(max(y0 + 1, 0), 63);
        int x0a = min(max(x0, 0), 63), x1a = min(max(x0 + 1, 0), 63);
        g_wt[bh * 576 + i] = make_float4(w00, w01, w10, w11);
        g_offp[bh * 576 + i] =
            make_ushort4((unsigned short)(y0a * 64 + x0a),
                         (unsigned short)(y0a * 64 + x1a),
                         (unsigned short)(y1a * 64 + x0a),
                         (unsigned short)(y1a * 64 + x1a));
    }
}

// ============================================================================
// Kernel 2 (sampler): barrier-free deformable gather -> bf16 hi/lo A tiles.
// grid = 256 (one image row = 64 pixels), block = 256. Each thread per chunk:
// 2 octets of (m, 8 consecutive k): 8 bilinear samples -> 1 STG.128 hi + lo.
// Also absorbs the weight split (old k0) in its prologue.
// ============================================================================
__global__ __launch_bounds__(256) void k2_sampler(
    const float* __restrict__ x, const float* __restrict__ wgt)
{
    const int tid = threadIdx.x;
    const int bh = blockIdx.x;

    // --- absorbed weight split: 73728 items over 65536 threads ---
    for (int i = blockIdx.x * 256 + tid; i < 73728; i += 65536) {
        int ch = i >> 12;
        int r = i & 4095;
        int o = r >> 5, kp = r & 31;
        float2 wv = *(const float2*)(wgt + o * 1152 + ch * 64 + kp * 2);
        uint32_t lw, hw = bf16split_hi(wv.x, wv.y, lw);
        uint32_t off = SWZ128((uint32_t)(o * 128 + kp * 4));
        *(uint32_t*)(g_wb + ch * 32768 + off) = hw;
        *(uint32_t*)(g_wb + ch * 32768 + 16384 + off) = lw;
    }

    __shared__ float4 s_wt[576];
    __shared__ ushort4 s_off[576];
    const int mbase = bh * 576;
    for (int i = tid; i < 576; i += 256) {
        s_wt[i] = g_wt[mbase + i];
        s_off[i] = g_offp[mbase + i];
    }
    __syncthreads();

    const int b = bh >> 6;
    const float* xb = x + b * CC * HH * WW;
    const int g = bh >> 1;
    const int mloc0 = (bh & 1) * 64;

    for (int ch = 0; ch < 18; ch++) {
#pragma unroll
        for (int it = 0; it < 2; it++) {
            int id = it * 256 + tid;      // 512 octets per chunk
            int w = id & 63;
            int o8 = id >> 6;             // 0..7
            uint32_t hiw[4], low[4];
#pragma unroll
            for (int jp = 0; jp < 4; jp++) {
                int k = ch * 64 + o8 * 8 + jp * 2;
                unsigned c0 = (unsigned)k / 9u;
                int t0 = k - c0 * 9;
                unsigned c1 = (unsigned)(k + 1) / 9u;
                int t1 = (k + 1) - c1 * 9;

                float4 w0 = s_wt[t0 * 64 + w];
                ushort4 o0 = s_off[t0 * 64 + w];
                const float* xp0 = xb + c0 * 4096;
                float v0 = w0.x * xp0[o0.x] + w0.y * xp0[o0.y]
                         + w0.z * xp0[o0.z] + w0.w * xp0[o0.w];

                float4 w1 = s_wt[t1 * 64 + w];
                ushort4 o1 = s_off[t1 * 64 + w];
                const float* xp1 = xb + c1 * 4096;
                float v1 = w1.x * xp1[o1.x] + w1.y * xp1[o1.y]
                         + w1.z * xp1[o1.z] + w1.w * xp1[o1.w];

                hiw[jp] = bf16split_hi(v0, v1, low[jp]);
            }
            size_t tbase = (size_t)(g * 18 + ch) * 16384;
            uint32_t off = SWZ128((uint32_t)((mloc0 + w) * 128 + o8 * 16));
            *(uint4*)(g_Ahi + tbase + off) =
                make_uint4(hiw[0], hiw[1], hiw[2], hiw[3]);
            *(uint4*)(g_Alo + tbase + off) =
                make_uint4(low[0], low[1], low[2], low[3]);
        }
    }
}

// ============================================================================
// Kernel 3 (GEMM): C[128m x 128n] per CTA, 3-stage cp.async pipeline over 18
// K-chunks of 64, split-bf16 3-pass mma.sync, BN + SiLU epilogue.
// grid = 128, block = 256 (8 warps, warp tile M64 x N32). 1 CTA/SM.
// Stage layout (64KB): Ahi 16K | Alo 16K | Bhi 16K | Blo 16K.
// ============================================================================
#define GSTAGE 65536
#define SMG_SC (3 * GSTAGE)
#define SMG_SH (SMG_SC + 512)
#define SMG_BYTES (SMG_SH + 512)

__device__ __forceinline__ void gemm_issue_stage(uint32_t sdst, int g, int ch,
                                                 int tid)
{
    size_t t = (size_t)(g * 18 + ch) * 16384;
#pragma unroll
    for (int it = 0; it < 4; it++) {
        int ln = (it * 256 + tid) * 16;
        cp_async16(sdst + ln, g_Ahi + t + ln);
    }
#pragma unroll
    for (int it = 0; it < 4; it++) {
        int ln = (it * 256 + tid) * 16;
        cp_async16(sdst + 16384 + ln, g_Alo + t + ln);
    }
    const char* bsrc = g_wb + ch * 32768;
#pragma unroll
    for (int it = 0; it < 8; it++) {
        int ln = (it * 256 + tid) * 16;
        cp_async16(sdst + 32768 + ln, bsrc + ln);
    }
}

__global__ __launch_bounds__(256, 1) void k3_gemm(
    const float* __restrict__ gamma, const float* __restrict__ beta,
    const float* __restrict__ mean, const float* __restrict__ var,
    float* __restrict__ out)
{
    extern __shared__ char sm[];
    const uint32_t sb = smem_u32(sm);
    const int tid = threadIdx.x;
    const int wid = tid >> 5, lid = tid & 31;
    const int blk = blockIdx.x;   // g
    const int b = blk >> 5;
    const int h0 = (blk & 31) * 2;

    float* s_sc = (float*)(sm + SMG_SC);
    float* s_sh = (float*)(sm + SMG_SH);
    if (tid < 128) {
        float sc = gamma[tid] * rsqrtf(var[tid] + 1e-5f);
        s_sc[tid] = sc;
        s_sh[tid] = beta[tid] - mean[tid] * sc;
    }

    // prologue: fill 3 stages
#pragma unroll
    for (int s = 0; s < 3; s++) {
        gemm_issue_stage(sb + s * GSTAGE, blk, s, tid);
        cp_commit();
    }

    const int wM = (wid & 1) * 64;
    const int wN = (wid >> 1) * 32;
    const int a_row = lid & 15;
    const int a_col = (lid >> 4) * 8;
    const int b_row = (lid & 7) + ((lid >> 4) << 3);
    const int b_col = ((lid >> 3) & 1) * 8;

    float acc[4][4][4];
#pragma unroll
    for (int mt = 0; mt < 4; mt++)
#pragma unroll
        for (int nt = 0; nt < 4; nt++)
#pragma unroll
            for (int i = 0; i < 4; i++) acc[mt][nt][i] = 0.f;

    int st = 0;
    for (int ch = 0; ch < 18; ch++) {
        cp_wait2();
        __syncthreads();
        const uint32_t baseA = sb + st * GSTAGE;

#pragma unroll
        for (int ks = 0; ks < 4; ks++) {
            uint32_t bhf[2][4], blf[2][4];
#pragma unroll
            for (int p2 = 0; p2 < 2; p2++) {
                uint32_t off = SWZ128((uint32_t)((wN + p2 * 16 + b_row) * 128 +
                                                 (ks * 16 + b_col) * 2));
                ldsm_x4(bhf[p2], baseA + 32768 + off);
                ldsm_x4(blf[p2], baseA + 49152 + off);
            }
#pragma unroll
            for (int mt = 0; mt < 4; mt++) {
                uint32_t ah[4], al[4];
                uint32_t off = SWZ128((uint32_t)((wM + mt * 16 + a_row) * 128 +
                                                 (ks * 16 + a_col) * 2));
                ldsm_x4(ah, baseA + off);
                ldsm_x4(al, baseA + 16384 + off);
#pragma unroll
                for (int nt = 0; nt < 4; nt++) {
                    const uint32_t* bhp = &bhf[nt >> 1][(nt & 1) * 2];
                    const uint32_t* blp = &blf[nt >> 1][(nt & 1) * 2];
                    mma_bf16(acc[mt][nt], ah, bhp);
                    mma_bf16(acc[mt][nt], ah, blp);
                    mma_bf16(acc[mt][nt], al, bhp);
                }
            }
        }

        __syncthreads();
        if (ch + 3 < 18) gemm_issue_stage(baseA, blk, ch + 3, tid);
        cp_commit();
        st = (st + 1 == 3) ? 0 : st + 1;
    }

    // epilogue: BN + SiLU + store
    const int g2 = lid >> 2, t2 = (lid & 3) * 2;
#pragma unroll
    for (int mt = 0; mt < 4; mt++) {
#pragma unroll
        for (int nt = 0; nt < 4; nt++) {
#pragma unroll
            for (int i = 0; i < 4; i++) {
                int m = wM + mt * 16 + g2 + ((i >> 1) ? 8 : 0);
                int n = wN + nt * 8 + t2 + (i & 1);
                float v = acc[mt][nt][i] * s_sc[n] + s_sh[n];
                v = v / (1.f + __expf(-v));
                int h = h0 + (m >> 6), w = m & 63;
                out[((b * OO + n) * HH + h) * WW + w] = v;
            }
        }
    }
}

extern "C" void kernel_launch(void* const* d_in, const int* in_sizes, int n_in,
                              void* d_out, int out_size)
{
    const float* x  = (const float*)d_in[0];
    const float* ow = (const float*)d_in[1];
    const float* ob = (const float*)d_in[2];
    const float* mw = (const float*)d_in[3];
    const float* mb = (const float*)d_in[4];
    const float* wg = (const float*)d_in[5];
    const float* gg = (const float*)d_in[6];
    const float* bt = (const float*)d_in[7];
    const float* mu = (const float*)d_in[8];
    const float* vr = (const float*)d_in[9];
    float* out = (float*)d_out;

    const int SM1 = (1152 * 28 + 4 * 28 * 64) * 4;  // 157,696 B
    cudaFuncSetAttribute(k1_sample_meta,
                         cudaFuncAttributeMaxDynamicSharedMemorySize, SM1);
    cudaFuncSetAttribute(k3_gemm,
                         cudaFuncAttributeMaxDynamicSharedMemorySize, SMG_BYTES);

    k1_sample_meta<<<BB * HH, 256, SM1>>>(x, ow, ob, mw, mb);
    k2_sampler<<<BB * HH, 256>>>(x, wg);
    k3_gemm<<<128, 256, SMG_BYTES>>>(gg, bt, mu, vr, out);
}

// round 7
// speedup vs baseline: 1.8863x; 1.3235x over previous
#include <cuda_runtime.h>
#include <cuda_bf16.h>
#include <cstdint>

// Problem constants (fixed by setup_inputs)
#define BB 4
#define CC 128
#define HH 64
#define WW 64
#define OO 128
#define TT 9
#define NSPLIT 8   // channel splits for k1a (16 channels each)

// Sampling metadata: per (b,h) row: 9 taps x 64 pixels.
__device__ float4  g_wt[BB * HH * TT * WW];   // bilinear weights * mask (0 if invalid)
__device__ ushort4 g_offp[BB * HH * TT * WW]; // clamped flat offsets (y*64+x), 4 corners
// Pre-split, pre-swizzled bf16 weights: [18 chunks][hi 16KB | lo 16KB]
__device__ __align__(16) char g_wb[18 * 32768];
// Partial conv sums: [split][bh][28 oc][64 w]
__device__ float g_part[NSPLIT * 256 * 28 * 64];

// ---------------------------------------------------------------------------
// helpers
// ---------------------------------------------------------------------------
__device__ __forceinline__ unsigned long long pack2(float a, float b) {
    unsigned long long r;
    asm("mov.b64 %0, {%1, %2};"
        : "=l"(r) : "r"(__float_as_uint(a)), "r"(__float_as_uint(b)));
    return r;
}
__device__ __forceinline__ void unpack2(unsigned long long v, float& a, float& b) {
    unsigned int lo, hi;
    asm("mov.b64 {%0, %1}, %2;" : "=r"(lo), "=r"(hi) : "l"(v));
    a = __uint_as_float(lo);
    b = __uint_as_float(hi);
}
__device__ __forceinline__ void fma2(unsigned long long& d,
                                     unsigned long long a,
                                     unsigned long long b) {
    asm("fma.rn.f32x2 %0, %1, %2, %0;" : "+l"(d) : "l"(a), "l"(b));
}
__device__ __forceinline__ uint32_t smem_u32(const void* p) {
    uint32_t a;
    asm("{ .reg .u64 t; cvta.to.shared.u64 t, %1; cvt.u32.u64 %0, t; }"
        : "=r"(a) : "l"(p));
    return a;
}
#define SWZ128(o) ((o) ^ (((o) >> 3) & 0x70))

__device__ __forceinline__ void ldsm_x4(uint32_t* r, uint32_t addr) {
    asm volatile("ldmatrix.sync.aligned.m8n8.x4.shared.b16 {%0,%1,%2,%3}, [%4];"
                 : "=r"(r[0]), "=r"(r[1]), "=r"(r[2]), "=r"(r[3]) : "r"(addr));
}
__device__ __forceinline__ void mma_bf16(float* c, const uint32_t* a,
                                         const uint32_t* b) {
    asm volatile("mma.sync.aligned.m16n8k16.row.col.f32.bf16.bf16.f32 "
                 "{%0,%1,%2,%3}, {%4,%5,%6,%7}, {%8,%9}, {%0,%1,%2,%3};"
                 : "+f"(c[0]), "+f"(c[1]), "+f"(c[2]), "+f"(c[3])
                 : "r"(a[0]), "r"(a[1]), "r"(a[2]), "r"(a[3]),
                   "r"(b[0]), "r"(b[1]));
}
__device__ __forceinline__ uint32_t bf16split_hi(float v0, float v1, uint32_t& lw) {
    __nv_bfloat16 h0 = __float2bfloat16(v0);
    __nv_bfloat16 h1 = __float2bfloat16(v1);
    __nv_bfloat16 l0 = __float2bfloat16(v0 - __bfloat162float(h0));
    __nv_bfloat16 l1 = __float2bfloat16(v1 - __bfloat162float(h1));
    lw = ((uint32_t)__bfloat16_as_ushort(l1) << 16) | __bfloat16_as_ushort(l0);
    return ((uint32_t)__bfloat16_as_ushort(h1) << 16) | __bfloat16_as_ushort(h0);
}
__device__ __forceinline__ void cp_async16(uint32_t smem_dst, const void* gsrc) {
    asm volatile("cp.async.cg.shared.global [%0], [%1], 16;"
                 :: "r"(smem_dst), "l"(gsrc) : "memory");
}
__device__ __forceinline__ void cp_commit() {
    asm volatile("cp.async.commit_group;" ::: "memory");
}
__device__ __forceinline__ void cp_wait0() {
    asm volatile("cp.async.wait_group 0;" ::: "memory");
}

// ============================================================================
// Kernel 0: split GEMM weights into bf16 hi/lo, pre-swizzled per-chunk tiles.
// ============================================================================
__global__ __launch_bounds__(256) void k0_split_weights(const float* __restrict__ wgt)
{
    int id = blockIdx.x * 256 + threadIdx.x;  // 73728 items
    int ch = id >> 12;
    int r = id & 4095;
    int o = r >> 5, kp = r & 31;
    float2 wv = *(const float2*)(wgt + o * 1152 + ch * 64 + kp * 2);
    uint32_t lw, hw = bf16split_hi(wv.x, wv.y, lw);
    uint32_t off = SWZ128((uint32_t)(o * 128 + kp * 4));
    *(uint32_t*)(g_wb + ch * 32768 + off) = hw;
    *(uint32_t*)(g_wb + ch * 32768 + 16384 + off) = lw;
}

// ============================================================================
// Kernel 1a: partial 27-channel conv. grid = (256 bh, 8 splits), block = 256
// (64 w x 4 cg, each cg = 4 channels). Static smem 44.8KB -> 4 CTAs/SM.
// Writes partial [28][64] sums per (split, bh) to g_part.
// ============================================================================
__global__ __launch_bounds__(256) void k1a_conv_partial(
    const float* __restrict__ x,
    const float* __restrict__ ow, const float* __restrict__ mw)
{
    __shared__ float wsm[144 * 28];      // [16 c x 9 taps][28]
    __shared__ float red[4 * 28 * 64];   // [cg][oc][w]

    const int bh = blockIdx.x;
    const int s = blockIdx.y;
    const int b = bh >> 6, h = bh & 63;
    const int tid = threadIdx.x;
    const int w = tid & 63, cg = tid >> 6;

    // stage this split's weight slice: rows s*144 .. s*144+144
    for (int i = tid; i < 27 * 144; i += 256) {
        int oc = i / 144;
        int r = i - oc * 144;
        int gr = s * 144 + r;
        float v = (oc < 18) ? ow[oc * 1152 + gr] : mw[(oc - 18) * 1152 + gr];
        wsm[r * 28 + oc] = v;
    }
    for (int i = tid; i < 144; i += 256) wsm[i * 28 + 27] = 0.f;
    __syncthreads();

    unsigned long long acc2[14];
#pragma unroll
    for (int q = 0; q < 14; q++) acc2[q] = 0ull;

    const float* xb = x + b * CC * HH * WW;
#pragma unroll
    for (int i = 0; i < 4; i++) {
        int cloc = cg * 4 + i;
        const float* xp = xb + (s * 16 + cloc) * HH * WW;
#pragma unroll
        for (int kh = 0; kh < 3; kh++) {
            int yy = h + kh - 1;
            if ((unsigned)yy >= (unsigned)HH) continue;
#pragma unroll
            for (int kw = 0; kw < 3; kw++) {
                int xx = w + kw - 1;
                if ((unsigned)xx >= (unsigned)WW) continue;
                float xv = xp[yy * WW + xx];
                unsigned long long xv2 = pack2(xv, xv);
                const ulonglong2* wp =
                    (const ulonglong2*)&wsm[(cloc * 9 + kh * 3 + kw) * 28];
#pragma unroll
                for (int q = 0; q < 7; q++) {
                    ulonglong2 u = wp[q];
                    fma2(acc2[2 * q], xv2, u.x);
                    fma2(acc2[2 * q + 1], xv2, u.y);
                }
            }
        }
    }

#pragma unroll
    for (int q = 0; q < 14; q++) {
        float a, b2;
        unpack2(acc2[q], a, b2);
        red[(cg * 28 + 2 * q) * 64 + w] = a;
        red[(cg * 28 + 2 * q + 1) * 64 + w] = b2;
    }
    __syncthreads();

    float* gp = g_part + (s * 256 + bh) * 1792;
    for (int i = tid; i < 1792; i += 256) {
        int oc = i >> 6, ww = i & 63;
        float v = red[(0 * 28 + oc) * 64 + ww] + red[(1 * 28 + oc) * 64 + ww]
                + red[(2 * 28 + oc) * 64 + ww] + red[(3 * 28 + oc) * 64 + ww];
        gp[i] = v;
    }
}

// ============================================================================
// Kernel 1b: reduce 8 splits + bias + sigmoid + bilinear sampling metadata.
// grid = 256 (bh), block = 256.
// ============================================================================
__global__ __launch_bounds__(256) void k1b_meta(
    const float* __restrict__ ob, const float* __restrict__ mb)
{
    const int bh = blockIdx.x;
    const int h = bh & 63;
    const int tid = threadIdx.x;

    for (int i = tid; i < TT * 64; i += 256) {
        int t = i >> 6, ww = i & 63;
        float s0 = 0.f, s1 = 0.f, s2 = 0.f;
#pragma unroll
        for (int s = 0; s < NSPLIT; s++) {
            const float* gp = g_part + (s * 256 + bh) * 1792;
            s0 += gp[(2 * t) * 64 + ww];
            s1 += gp[(2 * t + 1) * 64 + ww];
            s2 += gp[(18 + t) * 64 + ww];
        }
        float offy = s0 + ob[2 * t];
        float offx = s1 + ob[2 * t + 1];
        float m = 1.f / (1.f + __expf(-(s2 + mb[t])));

        int ii = t / 3;
        int jj = t - ii * 3;
        float py = (float)(h - 1 + ii) + offy;
        float px = (float)(ww - 1 + jj) + offx;
        float fy = floorf(py), fx = floorf(px);
        float ly = py - fy, lx = px - fx;
        int y0 = (int)fy, x0 = (int)fx;
        float hy = 1.f - ly, hx = 1.f - lx;
        float w00 = hy * hx * m, w01 = hy * lx * m;
        float w10 = ly * hx * m, w11 = ly * lx * m;
        bool vy0 = (unsigned)y0 < 64u;
        bool vy1 = (unsigned)(y0 + 1) < 64u;
        bool vx0 = (unsigned)x0 < 64u;
        bool vx1 = (unsigned)(x0 + 1) < 64u;
        if (!(vy0 && vx0)) w00 = 0.f;
        if (!(vy0 && vx1)) w01 = 0.f;
        if (!(vy1 && vx0)) w10 = 0.f;
        if (!(vy1 && vx1)) w11 = 0.f;
        int y0a = min(max(y0, 0), 63), y1a = min(max(y0 + 1, 0), 63);
        int x0a = min(max(x0, 0), 63), x1a = min(max(x0 + 1, 0), 63);
        g_wt[bh * 576 + i] = make_float4(w00, w01, w10, w11);
        g_offp[bh * 576 + i] =
            make_ushort4((unsigned short)(y0a * 64 + x0a),
                         (unsigned short)(y0a * 64 + x1a),
                         (unsigned short)(y1a * 64 + x0a),
                         (unsigned short)(y1a * 64 + x1a));
    }
}

// ============================================================================
// Kernel 2: fused deformable sampling (bf16 hi/lo) + mma.sync GEMM + BN + SiLU.
// (R4 design, proven ~70us: grid 256 rows, block 256, 2 CTAs/SM, double buffer,
//  A gathered in-kernel, B via cp.async from g_wb)
// ============================================================================
#define SM_WT  98304    // float4[576]
#define SM_OFF 107520   // ushort4[576]
#define SM_SC  112128   // float[128]
#define SM_SH  112640   // float[128]
#define SM2_BYTES 113152

__device__ __forceinline__ void stage_A(
    char* buf, const float* __restrict__ xb,
    const float4* __restrict__ s_wt, const ushort4* __restrict__ s_off,
    int k0, int tid)
{
    char* alo = buf + 8192;
#pragma unroll
    for (int it = 0; it < 8; it++) {
        int id = it * 256 + tid;
        int m = (id & 7) | (((id >> 5) & 7) << 3);
        int kp = ((id >> 3) & 3) | ((id >> 8) << 2);
        int k = k0 + kp * 2;

        unsigned c0 = (unsigned)k / 9u;
        int t0 = k - c0 * 9;
        unsigned c1 = (unsigned)(k + 1) / 9u;
        int t1 = (k + 1) - c1 * 9;

        float4 w0 = s_wt[t0 * 64 + m];
        ushort4 o0 = s_off[t0 * 64 + m];
        const float* xp0 = xb + c0 * 4096;
        float v0 = w0.x * xp0[o0.x] + w0.y * xp0[o0.y]
                 + w0.z * xp0[o0.z] + w0.w * xp0[o0.w];

        float4 w1 = s_wt[t1 * 64 + m];
        ushort4 o1 = s_off[t1 * 64 + m];
        const float* xp1 = xb + c1 * 4096;
        float v1 = w1.x * xp1[o1.x] + w1.y * xp1[o1.y]
                 + w1.z * xp1[o1.z] + w1.w * xp1[o1.w];

        uint32_t lw, hw = bf16split_hi(v0, v1, lw);
        uint32_t off = SWZ128((uint32_t)(m * 128 + kp * 4));
        *(uint32_t*)(buf + off) = hw;
        *(uint32_t*)(alo + off) = lw;
    }
}

__global__ __launch_bounds__(256, 2) void k2_deform_mma(
    const float* __restrict__ x,
    const float* __restrict__ gamma, const float* __restrict__ beta,
    const float* __restrict__ mean, const float* __restrict__ var,
    float* __restrict__ out)
{
    extern __shared__ char sm[];
    const uint32_t sb = smem_u32(sm);
    const int tid = threadIdx.x;
    const int wid = tid >> 5, lid = tid & 31;
    const int blk = blockIdx.x;
    const int b = blk >> 6;
    const int h = blk & 63;

    float4* s_wt = (float4*)(sm + SM_WT);
    ushort4* s_off = (ushort4*)(sm + SM_OFF);
    float* s_sc = (float*)(sm + SM_SC);
    float* s_sh = (float*)(sm + SM_SH);

    const int mbase = (b * 64 + h) * 576;
    for (int i = tid; i < 576; i += 256) {
        s_wt[i] = g_wt[mbase + i];
        s_off[i] = g_offp[mbase + i];
    }
    if (tid < 128) {
        float sc = gamma[tid] * rsqrtf(var[tid] + 1e-5f);
        s_sc[tid] = sc;
        s_sh[tid] = beta[tid] - mean[tid] * sc;
    }
    const float* xb = x + b * CC * HH * WW;
    __syncthreads();

    const int wM = (wid & 1) * 32;
    const int wN = (wid >> 1) * 32;
    const int a_row = lid & 15;
    const int a_col = (lid >> 4) * 8;
    const int b_row = (lid & 7) + ((lid >> 4) << 3);
    const int b_col = ((lid >> 3) & 1) * 8;

    float acc[2][4][4];
#pragma unroll
    for (int mt = 0; mt < 2; mt++)
#pragma unroll
        for (int nt = 0; nt < 4; nt++)
#pragma unroll
            for (int i = 0; i < 4; i++) acc[mt][nt][i] = 0.f;

    // prologue: stage chunk 0 into buf 0
    {
        uint32_t bsm = sb + 16384;
#pragma unroll
        for (int it = 0; it < 8; it++) {
            int ln = it * 256 + tid;
            cp_async16(bsm + ln * 16, g_wb + ln * 16);
        }
        cp_commit();
        stage_A(sm, xb, s_wt, s_off, 0, tid);
        cp_wait0();
    }
    __syncthreads();

    for (int ch = 0; ch < 18; ch++) {
        const int cur = ch & 1;
        const uint32_t baseA = sb + cur * 49152;
        char* nxt = sm + (cur ^ 1) * 49152;

        if (ch < 17) {
            uint32_t bsm = sb + (cur ^ 1) * 49152 + 16384;
            const char* gsrc = g_wb + (ch + 1) * 32768;
#pragma unroll
            for (int it = 0; it < 8; it++) {
                int ln = it * 256 + tid;
                cp_async16(bsm + ln * 16, gsrc + ln * 16);
            }
            cp_commit();
        }

#pragma unroll
        for (int ks = 0; ks < 4; ks++) {
            uint32_t ah[2][4], al[2][4];
#pragma unroll
            for (int mt = 0; mt < 2; mt++) {
                uint32_t off = SWZ128((uint32_t)((wM + mt * 16 + a_row) * 128 +
                                                 (ks * 16 + a_col) * 2));
                ldsm_x4(ah[mt], baseA + off);
                ldsm_x4(al[mt], baseA + 8192 + off);
            }
            uint32_t bhf[2][4], blf[2][4];
#pragma unroll
            for (int p = 0; p < 2; p++) {
                uint32_t off = SWZ128((uint32_t)((wN + p * 16 + b_row) * 128 +
                                                 (ks * 16 + b_col) * 2));
                ldsm_x4(bhf[p], baseA + 16384 + off);
                ldsm_x4(blf[p], baseA + 32768 + off);
            }
#pragma unroll
            for (int mt = 0; mt < 2; mt++)
#pragma unroll
                for (int nt = 0; nt < 4; nt++) {
                    const uint32_t* bhp = &bhf[nt >> 1][(nt & 1) * 2];
                    const uint32_t* blp = &blf[nt >> 1][(nt & 1) * 2];
                    mma_bf16(acc[mt][nt], ah[mt], bhp);
                    mma_bf16(acc[mt][nt], ah[mt], blp);
                    mma_bf16(acc[mt][nt], al[mt], bhp);
                }
        }

        if (ch < 17) stage_A(nxt, xb, s_wt, s_off, (ch + 1) * 64, tid);
        cp_wait0();
        __syncthreads();
    }

    // epilogue: BN + SiLU + store
    const int g = lid >> 2, t2 = (lid & 3) * 2;
#pragma unroll
    for (int mt = 0; mt < 2; mt++) {
#pragma unroll
        for (int nt = 0; nt < 4; nt++) {
#pragma unroll
            for (int i = 0; i < 4; i++) {
                int m = wM + mt * 16 + g + ((i >> 1) ? 8 : 0);
                int n = wN + nt * 8 + t2 + (i & 1);
                float v = acc[mt][nt][i] * s_sc[n] + s_sh[n];
                v = v / (1.f + __expf(-v));
                out[((b * OO + n) * HH + h) * WW + m] = v;
            }
        }
    }
}

extern "C" void kernel_launch(void* const* d_in, const int* in_sizes, int n_in,
                              void* d_out, int out_size)
{
    const float* x  = (const float*)d_in[0];
    const float* ow = (const float*)d_in[1];
    const float* ob = (const float*)d_in[2];
    const float* mw = (const float*)d_in[3];
    const float* mb = (const float*)d_in[4];
    const float* wg = (const float*)d_in[5];
    const float* gg = (const float*)d_in[6];
    const float* bt = (const float*)d_in[7];
    const float* mu = (const float*)d_in[8];
    const float* vr = (const float*)d_in[9];
    float* out = (float*)d_out;

    cudaFuncSetAttribute(k2_deform_mma,
                         cudaFuncAttributeMaxDynamicSharedMemorySize, SM2_BYTES);

    k0_split_weights<<<288, 256>>>(wg);
    k1a_conv_partial<<<dim3(256, NSPLIT), 256>>>(x, ow, mw);
    k1b_meta<<<256, 256>>>(ob, mb);
    k2_deform_mma<<<BB * HH, 256, SM2_BYTES>>>(x, gg, bt, mu, vr, out);
}

// round 8
// speedup vs baseline: 1.9717x; 1.0453x over previous
#include <cuda_runtime.h>
#include <cuda_bf16.h>
#include <cstdint>

// Problem constants (fixed by setup_inputs)
#define BB 4
#define CC 128
#define HH 64
#define WW 64
#define OO 128
#define TT 9
#define NSPLIT 8   // channel splits for k1a (16 channels each)

// Sampling metadata: per (b,h) row: 9 taps x 64 pixels.
__device__ float4  g_wt[BB * HH * TT * WW];   // bilinear weights * mask (0 if invalid)
__device__ ushort4 g_offp[BB * HH * TT * WW]; // clamped flat offsets (y*64+x), 4 corners
// Pre-split, pre-swizzled bf16 weights: [18 chunks][hi 16KB | lo 16KB]
__device__ __align__(16) char g_wb[18 * 32768];
// Partial conv sums: [split][bh][28 oc][64 w]
__device__ float g_part[NSPLIT * 256 * 28 * 64];

// ---------------------------------------------------------------------------
// helpers
// ---------------------------------------------------------------------------
__device__ __forceinline__ unsigned long long pack2(float a, float b) {
    unsigned long long r;
    asm("mov.b64 %0, {%1, %2};"
        : "=l"(r) : "r"(__float_as_uint(a)), "r"(__float_as_uint(b)));
    return r;
}
__device__ __forceinline__ void unpack2(unsigned long long v, float& a, float& b) {
    unsigned int lo, hi;
    asm("mov.b64 {%0, %1}, %2;" : "=r"(lo), "=r"(hi) : "l"(v));
    a = __uint_as_float(lo);
    b = __uint_as_float(hi);
}
__device__ __forceinline__ void fma2(unsigned long long& d,
                                     unsigned long long a,
                                     unsigned long long b) {
    asm("fma.rn.f32x2 %0, %1, %2, %0;" : "+l"(d) : "l"(a), "l"(b));
}
__device__ __forceinline__ uint32_t smem_u32(const void* p) {
    uint32_t a;
    asm("{ .reg .u64 t; cvta.to.shared.u64 t, %1; cvt.u32.u64 %0, t; }"
        : "=r"(a) : "l"(p));
    return a;
}
#define SWZ128(o) ((o) ^ (((o) >> 3) & 0x70))

__device__ __forceinline__ void ldsm_x4(uint32_t* r, uint32_t addr) {
    asm volatile("ldmatrix.sync.aligned.m8n8.x4.shared.b16 {%0,%1,%2,%3}, [%4];"
                 : "=r"(r[0]), "=r"(r[1]), "=r"(r[2]), "=r"(r[3]) : "r"(addr));
}
__device__ __forceinline__ void mma_bf16(float* c, const uint32_t* a,
                                         const uint32_t* b) {
    asm volatile("mma.sync.aligned.m16n8k16.row.col.f32.bf16.bf16.f32 "
                 "{%0,%1,%2,%3}, {%4,%5,%6,%7}, {%8,%9}, {%0,%1,%2,%3};"
                 : "+f"(c[0]), "+f"(c[1]), "+f"(c[2]), "+f"(c[3])
                 : "r"(a[0]), "r"(a[1]), "r"(a[2]), "r"(a[3]),
                   "r"(b[0]), "r"(b[1]));
}
__device__ __forceinline__ uint32_t bf16split_hi(float v0, float v1, uint32_t& lw) {
    __nv_bfloat16 h0 = __float2bfloat16(v0);
    __nv_bfloat16 h1 = __float2bfloat16(v1);
    __nv_bfloat16 l0 = __float2bfloat16(v0 - __bfloat162float(h0));
    __nv_bfloat16 l1 = __float2bfloat16(v1 - __bfloat162float(h1));
    lw = ((uint32_t)__bfloat16_as_ushort(l1) << 16) | __bfloat16_as_ushort(l0);
    return ((uint32_t)__bfloat16_as_ushort(h1) << 16) | __bfloat16_as_ushort(h0);
}
__device__ __forceinline__ void cp_async16(uint32_t smem_dst, const void* gsrc) {
    asm volatile("cp.async.cg.shared.global [%0], [%1], 16;"
                 :: "r"(smem_dst), "l"(gsrc) : "memory");
}
__device__ __forceinline__ void cp_commit() {
    asm volatile("cp.async.commit_group;" ::: "memory");
}
__device__ __forceinline__ void cp_wait0() {
    asm volatile("cp.async.wait_group 0;" ::: "memory");
}

// ============================================================================
// Kernel 1a: partial 27-channel conv. grid = (256 bh, 8 splits), block = 256.
// (proven R7)
// ============================================================================
__global__ __launch_bounds__(256) void k1a_conv_partial(
    const float* __restrict__ x,
    const float* __restrict__ ow, const float* __restrict__ mw)
{
    __shared__ float wsm[144 * 28];      // [16 c x 9 taps][28]
    __shared__ float red[4 * 28 * 64];   // [cg][oc][w]

    const int bh = blockIdx.x;
    const int s = blockIdx.y;
    const int b = bh >> 6, h = bh & 63;
    const int tid = threadIdx.x;
    const int w = tid & 63, cg = tid >> 6;

    for (int i = tid; i < 27 * 144; i += 256) {
        int oc = i / 144;
        int r = i - oc * 144;
        int gr = s * 144 + r;
        float v = (oc < 18) ? ow[oc * 1152 + gr] : mw[(oc - 18) * 1152 + gr];
        wsm[r * 28 + oc] = v;
    }
    for (int i = tid; i < 144; i += 256) wsm[i * 28 + 27] = 0.f;
    __syncthreads();

    unsigned long long acc2[14];
#pragma unroll
    for (int q = 0; q < 14; q++) acc2[q] = 0ull;

    const float* xb = x + b * CC * HH * WW;
#pragma unroll
    for (int i = 0; i < 4; i++) {
        int cloc = cg * 4 + i;
        const float* xp = xb + (s * 16 + cloc) * HH * WW;
#pragma unroll
        for (int kh = 0; kh < 3; kh++) {
            int yy = h + kh - 1;
            if ((unsigned)yy >= (unsigned)HH) continue;
#pragma unroll
            for (int kw = 0; kw < 3; kw++) {
                int xx = w + kw - 1;
                if ((unsigned)xx >= (unsigned)WW) continue;
                float xv = xp[yy * WW + xx];
                unsigned long long xv2 = pack2(xv, xv);
                const ulonglong2* wp =
                    (const ulonglong2*)&wsm[(cloc * 9 + kh * 3 + kw) * 28];
#pragma unroll
                for (int q = 0; q < 7; q++) {
                    ulonglong2 u = wp[q];
                    fma2(acc2[2 * q], xv2, u.x);
                    fma2(acc2[2 * q + 1], xv2, u.y);
                }
            }
        }
    }

#pragma unroll
    for (int q = 0; q < 14; q++) {
        float a, b2;
        unpack2(acc2[q], a, b2);
        red[(cg * 28 + 2 * q) * 64 + w] = a;
        red[(cg * 28 + 2 * q + 1) * 64 + w] = b2;
    }
    __syncthreads();

    float* gp = g_part + (s * 256 + bh) * 1792;
    for (int i = tid; i < 1792; i += 256) {
        int oc = i >> 6, ww = i & 63;
        float v = red[(0 * 28 + oc) * 64 + ww] + red[(1 * 28 + oc) * 64 + ww]
                + red[(2 * 28 + oc) * 64 + ww] + red[(3 * 28 + oc) * 64 + ww];
        gp[i] = v;
    }
}

// ============================================================================
// Kernel 1b: reduce splits + bias + sigmoid + bilinear metadata; also absorbs
// the GEMM-weight bf16 hi/lo split (old k0: 288 items per CTA).
// grid = 256 (bh), block = 256.
// ============================================================================
__global__ __launch_bounds__(256) void k1b_meta(
    const float* __restrict__ ob, const float* __restrict__ mb,
    const float* __restrict__ wgt)
{
    const int bh = blockIdx.x;
    const int h = bh & 63;
    const int tid = threadIdx.x;

    // absorbed weight split: 73728 items over 65536 threads
    for (int i = bh * 256 + tid; i < 73728; i += 65536) {
        int ch = i >> 12;
        int r = i & 4095;
        int o = r >> 5, kp = r & 31;
        float2 wv = *(const float2*)(wgt + o * 1152 + ch * 64 + kp * 2);
        uint32_t lw, hw = bf16split_hi(wv.x, wv.y, lw);
        uint32_t off = SWZ128((uint32_t)(o * 128 + kp * 4));
        *(uint32_t*)(g_wb + ch * 32768 + off) = hw;
        *(uint32_t*)(g_wb + ch * 32768 + 16384 + off) = lw;
    }

    for (int i = tid; i < TT * 64; i += 256) {
        int t = i >> 6, ww = i & 63;
        float s0 = 0.f, s1 = 0.f, s2 = 0.f;
#pragma unroll
        for (int s = 0; s < NSPLIT; s++) {
            const float* gp = g_part + (s * 256 + bh) * 1792;
            s0 += gp[(2 * t) * 64 + ww];
            s1 += gp[(2 * t + 1) * 64 + ww];
            s2 += gp[(18 + t) * 64 + ww];
        }
        float offy = s0 + ob[2 * t];
        float offx = s1 + ob[2 * t + 1];
        float m = 1.f / (1.f + __expf(-(s2 + mb[t])));

        int ii = t / 3;
        int jj = t - ii * 3;
        float py = (float)(h - 1 + ii) + offy;
        float px = (float)(ww - 1 + jj) + offx;
        float fy = floorf(py), fx = floorf(px);
        float ly = py - fy, lx = px - fx;
        int y0 = (int)fy, x0 = (int)fx;
        float hy = 1.f - ly, hx = 1.f - lx;
        float w00 = hy * hx * m, w01 = hy * lx * m;
        float w10 = ly * hx * m, w11 = ly * lx * m;
        bool vy0 = (unsigned)y0 < 64u;
        bool vy1 = (unsigned)(y0 + 1) < 64u;
        bool vx0 = (unsigned)x0 < 64u;
        bool vx1 = (unsigned)(x0 + 1) < 64u;
        if (!(vy0 && vx0)) w00 = 0.f;
        if (!(vy0 && vx1)) w01 = 0.f;
        if (!(vy1 && vx0)) w10 = 0.f;
        if (!(vy1 && vx1)) w11 = 0.f;
        int y0a = min(max(y0, 0), 63), y1a = min(max(y0 + 1, 0), 63);
        int x0a = min(max(x0, 0), 63), x1a = min(max(x0 + 1, 0), 63);
        g_wt[bh * 576 + i] = make_float4(w00, w01, w10, w11);
        g_offp[bh * 576 + i] =
            make_ushort4((unsigned short)(y0a * 64 + x0a),
                         (unsigned short)(y0a * 64 + x1a),
                         (unsigned short)(y1a * 64 + x0a),
                         (unsigned short)(y1a * 64 + x1a));
    }
}

// ============================================================================
// Kernel 2: fused deformable sampling + mma.sync GEMM + BN + SiLU, with the
// gather software-pipelined across the MMA blocks.
// grid = 256 rows, block = 256, 2 CTAs/SM, double-buffered chunks of K=64.
// ============================================================================
#define SM_WT  98304    // float4[576]
#define SM_OFF 107520   // ushort4[576]
#define SM_SC  112128   // float[128]
#define SM_SH  112640   // float[128]
#define SM2_BYTES 113152

// Issue 16 corner LDGs for group grp (iterations 2*grp, 2*grp+1) into pf[16].
__device__ __forceinline__ void issueA(
    float* pf, const float* __restrict__ xb,
    const ushort4* __restrict__ s_off, int k0, int grp, int tid)
{
#pragma unroll
    for (int j = 0; j < 2; j++) {
        int id = (grp * 2 + j) * 256 + tid;
        int m = (id & 7) | (((id >> 5) & 7) << 3);
        int kp = ((id >> 3) & 3) | ((id >> 8) << 2);
        int k = k0 + kp * 2;
#pragma unroll
        for (int s2 = 0; s2 < 2; s2++) {
            int kk = k + s2;
            unsigned c = (unsigned)kk / 9u;
            int t = kk - c * 9;
            ushort4 o = s_off[t * 64 + m];
            const float* xp = xb + c * 4096;
            float* p = pf + (j * 2 + s2) * 4;
            p[0] = xp[o.x];
            p[1] = xp[o.y];
            p[2] = xp[o.z];
            p[3] = xp[o.w];
        }
    }
}

// Consume group grp: weights from smem, dot, bf16 split, STS into buf.
__device__ __forceinline__ void consumeA(
    char* buf, const float* pf,
    const float4* __restrict__ s_wt, int k0, int grp, int tid)
{
    char* alo = buf + 8192;
#pragma unroll
    for (int j = 0; j < 2; j++) {
        int id = (grp * 2 + j) * 256 + tid;
        int m = (id & 7) | (((id >> 5) & 7) << 3);
        int kp = ((id >> 3) & 3) | ((id >> 8) << 2);
        int k = k0 + kp * 2;
        float v[2];
#pragma unroll
        for (int s2 = 0; s2 < 2; s2++) {
            int kk = k + s2;
            unsigned c = (unsigned)kk / 9u;
            int t = kk - c * 9;
            float4 w = s_wt[t * 64 + m];
            const float* p = pf + (j * 2 + s2) * 4;
            v[s2] = w.x * p[0] + w.y * p[1] + w.z * p[2] + w.w * p[3];
        }
        uint32_t lw, hw = bf16split_hi(v[0], v[1], lw);
        uint32_t off = SWZ128((uint32_t)(m * 128 + kp * 4));
        *(uint32_t*)(buf + off) = hw;
        *(uint32_t*)(alo + off) = lw;
    }
}

__global__ __launch_bounds__(256, 2) void k2_deform_mma(
    const float* __restrict__ x,
    const float* __restrict__ gamma, const float* __restrict__ beta,
    const float* __restrict__ mean, const float* __restrict__ var,
    float* __restrict__ out)
{
    extern __shared__ char sm[];
    const uint32_t sb = smem_u32(sm);
    const int tid = threadIdx.x;
    const int wid = tid >> 5, lid = tid & 31;
    const int blk = blockIdx.x;
    const int b = blk >> 6;
    const int h = blk & 63;

    float4* s_wt = (float4*)(sm + SM_WT);
    ushort4* s_off = (ushort4*)(sm + SM_OFF);
    float* s_sc = (float*)(sm + SM_SC);
    float* s_sh = (float*)(sm + SM_SH);

    const int mbase = (b * 64 + h) * 576;
    for (int i = tid; i < 576; i += 256) {
        s_wt[i] = g_wt[mbase + i];
        s_off[i] = g_offp[mbase + i];
    }
    if (tid < 128) {
        float sc = gamma[tid] * rsqrtf(var[tid] + 1e-5f);
        s_sc[tid] = sc;
        s_sh[tid] = beta[tid] - mean[tid] * sc;
    }
    const float* xb = x + b * CC * HH * WW;
    __syncthreads();

    const int wM = (wid & 1) * 32;
    const int wN = (wid >> 1) * 32;
    const int a_row = lid & 15;
    const int a_col = (lid >> 4) * 8;
    const int b_row = (lid & 7) + ((lid >> 4) << 3);
    const int b_col = ((lid >> 3) & 1) * 8;

    float acc[2][4][4];
#pragma unroll
    for (int mt = 0; mt < 2; mt++)
#pragma unroll
        for (int nt = 0; nt < 4; nt++)
#pragma unroll
            for (int i = 0; i < 4; i++) acc[mt][nt][i] = 0.f;

    float pf[16];

    // prologue: stage chunk 0 into buf 0 (exposed once)
    {
        uint32_t bsm = sb + 16384;
#pragma unroll
        for (int it = 0; it < 8; it++) {
            int ln = it * 256 + tid;
            cp_async16(bsm + ln * 16, g_wb + ln * 16);
        }
        cp_commit();
#pragma unroll
        for (int g = 0; g < 4; g++) {
            issueA(pf, xb, s_off, 0, g, tid);
            consumeA(sm, pf, s_wt, 0, g, tid);
        }
        cp_wait0();
    }
    __syncthreads();

    for (int ch = 0; ch < 18; ch++) {
        const int cur = ch & 1;
        const uint32_t baseA = sb + cur * 49152;
        char* nxt = sm + (cur ^ 1) * 49152;
        const int kn = (ch + 1) * 64;
        const bool more = (ch < 17);

        if (more) {
            uint32_t bsm = sb + (cur ^ 1) * 49152 + 16384;
            const char* gsrc = g_wb + (ch + 1) * 32768;
#pragma unroll
            for (int it = 0; it < 8; it++) {
                int ln = it * 256 + tid;
                cp_async16(bsm + ln * 16, gsrc + ln * 16);
            }
            cp_commit();
            issueA(pf, xb, s_off, kn, 0, tid);   // group 0 in flight
        }

#pragma unroll
        for (int ks = 0; ks < 4; ks++) {
            uint32_t ah[2][4], al[2][4];
#pragma unroll
            for (int mt = 0; mt < 2; mt++) {
                uint32_t off = SWZ128((uint32_t)((wM + mt * 16 + a_row) * 128 +
                                                 (ks * 16 + a_col) * 2));
                ldsm_x4(ah[mt], baseA + off);
                ldsm_x4(al[mt], baseA + 8192 + off);
            }
            uint32_t bhf[2][4], blf[2][4];
#pragma unroll
            for (int p = 0; p < 2; p++) {
                uint32_t off = SWZ128((uint32_t)((wN + p * 16 + b_row) * 128 +
                                                 (ks * 16 + b_col) * 2));
                ldsm_x4(bhf[p], baseA + 16384 + off);
                ldsm_x4(blf[p], baseA + 32768 + off);
            }
#pragma unroll
            for (int mt = 0; mt < 2; mt++)
#pragma unroll
                for (int nt = 0; nt < 4; nt++) {
                    const uint32_t* bhp = &bhf[nt >> 1][(nt & 1) * 2];
                    const uint32_t* blp = &blf[nt >> 1][(nt & 1) * 2];
                    mma_bf16(acc[mt][nt], ah[mt], bhp);
                    mma_bf16(acc[mt][nt], ah[mt], blp);
                    mma_bf16(acc[mt][nt], al[mt], bhp);
                }

            if (more) {
                consumeA(nxt, pf, s_wt, kn, ks, tid);
                if (ks < 3) issueA(pf, xb, s_off, kn, ks + 1, tid);
            }
        }

        cp_wait0();
        __syncthreads();
    }

    // epilogue: BN + SiLU + store
    const int g = lid >> 2, t2 = (lid & 3) * 2;
#pragma unroll
    for (int mt = 0; mt < 2; mt++) {
#pragma unroll
        for (int nt = 0; nt < 4; nt++) {
#pragma unroll
            for (int i = 0; i < 4; i++) {
                int m = wM + mt * 16 + g + ((i >> 1) ? 8 : 0);
                int n = wN + nt * 8 + t2 + (i & 1);
                float v = acc[mt][nt][i] * s_sc[n] + s_sh[n];
                v = v / (1.f + __expf(-v));
                out[((b * OO + n) * HH + h) * WW + m] = v;
            }
        }
    }
}

extern "C" void kernel_launch(void* const* d_in, const int* in_sizes, int n_in,
                              void* d_out, int out_size)
{
    const float* x  = (const float*)d_in[0];
    const float* ow = (const float*)d_in[1];
    const float* ob = (const float*)d_in[2];
    const float* mw = (const float*)d_in[3];
    const float* mb = (const float*)d_in[4];
    const float* wg = (const float*)d_in[5];
    const float* gg = (const float*)d_in[6];
    const float* bt = (const float*)d_in[7];
    const float* mu = (const float*)d_in[8];
    const float* vr = (const float*)d_in[9];
    float* out = (float*)d_out;

    cudaFuncSetAttribute(k2_deform_mma,
                         cudaFuncAttributeMaxDynamicSharedMemorySize, SM2_BYTES);

    k1a_conv_partial<<<dim3(256, NSPLIT), 256>>>(x, ow, mw);
    k1b_meta<<<256, 256>>>(ob, mb, wg);
    k2_deform_mma<<<BB * HH, 256, SM2_BYTES>>>(x, gg, bt, mu, vr, out);
}

// round 9
// speedup vs baseline: 2.0775x; 1.0536x over previous
#include <cuda_runtime.h>
#include <cuda_bf16.h>
#include <cstdint>

// Problem constants (fixed by setup_inputs)
#define BB 4
#define CC 128
#define HH 64
#define WW 64
#define OO 128
#define TT 9

// Sampling metadata: per (b,h) row: 9 taps x 64 pixels.
__device__ float4  g_wt[BB * HH * TT * WW];   // bilinear weights * mask (0 if invalid)
__device__ ushort4 g_offp[BB * HH * TT * WW]; // clamped flat offsets (y*64+x), 4 corners
// Pre-split, pre-swizzled bf16 GEMM weights: [18 chunks][hi 16KB | lo 16KB]
__device__ __align__(16) char g_wb[18 * 32768];
// Pre-split, pre-swizzled bf16 conv weights (27 oc padded to 32):
// [18 chunks][hi 4KB | lo 4KB]
__device__ __align__(16) char g_wbc[18 * 8192];
// Conv output sums (no bias): [bh][28 oc (27 used)][64 w]
__device__ float g_conv[256 * 28 * 64];

// ---------------------------------------------------------------------------
// helpers
// ---------------------------------------------------------------------------
__device__ __forceinline__ uint32_t smem_u32(const void* p) {
    uint32_t a;
    asm("{ .reg .u64 t; cvta.to.shared.u64 t, %1; cvt.u32.u64 %0, t; }"
        : "=r"(a) : "l"(p));
    return a;
}
#define SWZ128(o) ((o) ^ (((o) >> 3) & 0x70))

__device__ __forceinline__ void ldsm_x4(uint32_t* r, uint32_t addr) {
    asm volatile("ldmatrix.sync.aligned.m8n8.x4.shared.b16 {%0,%1,%2,%3}, [%4];"
                 : "=r"(r[0]), "=r"(r[1]), "=r"(r[2]), "=r"(r[3]) : "r"(addr));
}
__device__ __forceinline__ void mma_bf16(float* c, const uint32_t* a,
                                         const uint32_t* b) {
    asm volatile("mma.sync.aligned.m16n8k16.row.col.f32.bf16.bf16.f32 "
                 "{%0,%1,%2,%3}, {%4,%5,%6,%7}, {%8,%9}, {%0,%1,%2,%3};"
                 : "+f"(c[0]), "+f"(c[1]), "+f"(c[2]), "+f"(c[3])
                 : "r"(a[0]), "r"(a[1]), "r"(a[2]), "r"(a[3]),
                   "r"(b[0]), "r"(b[1]));
}
__device__ __forceinline__ uint32_t bf16split_hi(float v0, float v1, uint32_t& lw) {
    __nv_bfloat16 h0 = __float2bfloat16(v0);
    __nv_bfloat16 h1 = __float2bfloat16(v1);
    __nv_bfloat16 l0 = __float2bfloat16(v0 - __bfloat162float(h0));
    __nv_bfloat16 l1 = __float2bfloat16(v1 - __bfloat162float(h1));
    lw = ((uint32_t)__bfloat16_as_ushort(l1) << 16) | __bfloat16_as_ushort(l0);
    return ((uint32_t)__bfloat16_as_ushort(h1) << 16) | __bfloat16_as_ushort(h0);
}
__device__ __forceinline__ void cp_async16(uint32_t smem_dst, const void* gsrc) {
    asm volatile("cp.async.cg.shared.global [%0], [%1], 16;"
                 :: "r"(smem_dst), "l"(gsrc) : "memory");
}
__device__ __forceinline__ void cp_commit() {
    asm volatile("cp.async.commit_group;" ::: "memory");
}
__device__ __forceinline__ void cp_wait0() {
    asm volatile("cp.async.wait_group 0;" ::: "memory");
}

// ============================================================================
// Kernel 0: weight prep. CTAs 0..287: GEMM weights -> g_wb.
// CTAs 288..359: conv weights (27 oc padded to 32) -> g_wbc.
// ============================================================================
__global__ __launch_bounds__(256) void k0_prep(
    const float* __restrict__ wgt,
    const float* __restrict__ ow, const float* __restrict__ mw)
{
    const int blk = blockIdx.x;
    if (blk < 288) {
        int id = blk * 256 + threadIdx.x;  // 73728 items
        int ch = id >> 12;
        int r = id & 4095;
        int o = r >> 5, kp = r & 31;
        float2 wv = *(const float2*)(wgt + o * 1152 + ch * 64 + kp * 2);
        uint32_t lw, hw = bf16split_hi(wv.x, wv.y, lw);
        uint32_t off = SWZ128((uint32_t)(o * 128 + kp * 4));
        *(uint32_t*)(g_wb + ch * 32768 + off) = hw;
        *(uint32_t*)(g_wb + ch * 32768 + 16384 + off) = lw;
    } else {
        int id = (blk - 288) * 256 + threadIdx.x;  // 18432 items
        int ch = id >> 10;
        int r = id & 1023;
        int oc = r >> 5, kp = r & 31;
        int k = ch * 64 + kp * 2;
        float v0 = 0.f, v1 = 0.f;
        if (oc < 18) {
            v0 = ow[oc * 1152 + k];
            v1 = ow[oc * 1152 + k + 1];
        } else if (oc < 27) {
            v0 = mw[(oc - 18) * 1152 + k];
            v1 = mw[(oc - 18) * 1152 + k + 1];
        }
        uint32_t lw, hw = bf16split_hi(v0, v1, lw);
        uint32_t off = SWZ128((uint32_t)(oc * 128 + kp * 4));
        *(uint32_t*)(g_wbc + ch * 8192 + off) = hw;
        *(uint32_t*)(g_wbc + ch * 8192 + 4096 + off) = lw;
    }
}

// ============================================================================
// Kernel 1g: 27-channel conv as implicit GEMM (im2col, gather-free staging).
// grid = 128 (2 image rows, M=128), block = 256 (8 warps, warp M32 x N16).
// N = 32 (27 used), K = 1152 in 18 chunks of 64. Double-buffered smem:
// stage = Ahi 16K | Alo 16K | Bhi 4K | Blo 4K = 40KB; 2 stages = 80KB.
// Output: fp32 conv sums -> g_conv[bh][28][64].
// ============================================================================
#define CSTG 40960
#define SMC_BYTES (2 * CSTG)

__device__ __forceinline__ void stage_Ac(
    char* buf, const float* __restrict__ xb, int h0, int k0, int tid)
{
    char* alo = buf + 16384;
#pragma unroll 4
    for (int it = 0; it < 16; it++) {
        int id = it * 256 + tid;
        int m = (id & 7) | (((id >> 5) & 15) << 3);
        int kp = ((id >> 3) & 3) | ((id >> 9) << 2);
        int k = k0 + kp * 2;
        float v[2];
#pragma unroll
        for (int s2 = 0; s2 < 2; s2++) {
            int kk = k + s2;
            unsigned c = (unsigned)kk / 9u;
            int t = kk - c * 9;
            int ii = t / 3;
            int jj = t - ii * 3;
            int y = h0 + (m >> 6) + ii - 1;
            int xw = (m & 63) + jj - 1;
            bool valid = ((unsigned)y < 64u) && ((unsigned)xw < 64u);
            v[s2] = valid ? xb[c * 4096 + y * 64 + xw] : 0.f;
        }
        uint32_t lw, hw = bf16split_hi(v[0], v[1], lw);
        uint32_t off = SWZ128((uint32_t)(m * 128 + kp * 4));
        *(uint32_t*)(buf + off) = hw;
        *(uint32_t*)(alo + off) = lw;
    }
}

__global__ __launch_bounds__(256, 1) void k1g_conv_mma(const float* __restrict__ x)
{
    extern __shared__ char sm[];
    const uint32_t sb = smem_u32(sm);
    const int tid = threadIdx.x;
    const int wid = tid >> 5, lid = tid & 31;
    const int blk = blockIdx.x;
    const int b = blk >> 5;
    const int h0 = (blk & 31) * 2;
    const float* xb = x + b * CC * HH * WW;

    const int wM = (wid & 3) * 32;
    const int wN = (wid >> 2) * 16;
    const int a_row = lid & 15;
    const int a_col = (lid >> 4) * 8;
    const int b_row = (lid & 7) + ((lid >> 4) << 3);
    const int b_col = ((lid >> 3) & 1) * 8;

    float acc[2][2][4];
#pragma unroll
    for (int mt = 0; mt < 2; mt++)
#pragma unroll
        for (int nt = 0; nt < 2; nt++)
#pragma unroll
            for (int i = 0; i < 4; i++) acc[mt][nt][i] = 0.f;

    // prologue: stage chunk 0 into buf 0
    {
        uint32_t bsm = sb + 32768;
#pragma unroll
        for (int it = 0; it < 2; it++) {
            int ln = it * 256 + tid;
            cp_async16(bsm + ln * 16, g_wbc + ln * 16);
        }
        cp_commit();
        stage_Ac(sm, xb, h0, 0, tid);
        cp_wait0();
    }
    __syncthreads();

    for (int ch = 0; ch < 18; ch++) {
        const int cur = ch & 1;
        const uint32_t baseA = sb + cur * CSTG;
        char* nxt = sm + (cur ^ 1) * CSTG;

        if (ch < 17) {
            uint32_t bsm = sb + (cur ^ 1) * CSTG + 32768;
            const char* gsrc = g_wbc + (ch + 1) * 8192;
#pragma unroll
            for (int it = 0; it < 2; it++) {
                int ln = it * 256 + tid;
                cp_async16(bsm + ln * 16, gsrc + ln * 16);
            }
            cp_commit();
        }

#pragma unroll
        for (int ks = 0; ks < 4; ks++) {
            uint32_t bhf[4], blf[4];
            {
                uint32_t off = SWZ128((uint32_t)((wN + b_row) * 128 +
                                                 (ks * 16 + b_col) * 2));
                ldsm_x4(bhf, baseA + 32768 + off);
                ldsm_x4(blf, baseA + 36864 + off);
            }
#pragma unroll
            for (int mt = 0; mt < 2; mt++) {
                uint32_t ah[4], al[4];
                uint32_t off = SWZ128((uint32_t)((wM + mt * 16 + a_row) * 128 +
                                                 (ks * 16 + a_col) * 2));
                ldsm_x4(ah, baseA + off);
                ldsm_x4(al, baseA + 16384 + off);
#pragma unroll
                for (int nt = 0; nt < 2; nt++) {
                    const uint32_t* bhp = &bhf[nt * 2];
                    const uint32_t* blp = &blf[nt * 2];
                    mma_bf16(acc[mt][nt], ah, bhp);
                    mma_bf16(acc[mt][nt], ah, blp);
                    mma_bf16(acc[mt][nt], al, bhp);
                }
            }
        }

        if (ch < 17) stage_Ac(nxt, xb, h0, (ch + 1) * 64, tid);
        cp_wait0();
        __syncthreads();
    }

    // epilogue: write fp32 conv sums
    const int g = lid >> 2, t2 = (lid & 3) * 2;
#pragma unroll
    for (int mt = 0; mt < 2; mt++) {
#pragma unroll
        for (int nt = 0; nt < 2; nt++) {
#pragma unroll
            for (int i = 0; i < 4; i++) {
                int n = wN + nt * 8 + t2 + (i & 1);
                if (n >= 27) continue;
                int m = wM + mt * 16 + g + ((i >> 1) ? 8 : 0);
                int hh = h0 + (m >> 6), w = m & 63;
                g_conv[(b * 64 + hh) * 1792 + n * 64 + w] = acc[mt][nt][i];
            }
        }
    }
}

// ============================================================================
// Kernel 1b: bias + sigmoid + bilinear sampling metadata from g_conv.
// grid = 256 (bh), block = 256.
// ============================================================================
__global__ __launch_bounds__(256) void k1b_meta(
    const float* __restrict__ ob, const float* __restrict__ mb)
{
    const int bh = blockIdx.x;
    const int h = bh & 63;
    const int tid = threadIdx.x;
    const float* gp = g_conv + bh * 1792;

    for (int i = tid; i < TT * 64; i += 256) {
        int t = i >> 6, ww = i & 63;
        float s0 = gp[(2 * t) * 64 + ww];
        float s1 = gp[(2 * t + 1) * 64 + ww];
        float s2 = gp[(18 + t) * 64 + ww];
        float offy = s0 + ob[2 * t];
        float offx = s1 + ob[2 * t + 1];
        float m = 1.f / (1.f + __expf(-(s2 + mb[t])));

        int ii = t / 3;
        int jj = t - ii * 3;
        float py = (float)(h - 1 + ii) + offy;
        float px = (float)(ww - 1 + jj) + offx;
        float fy = floorf(py), fx = floorf(px);
        float ly = py - fy, lx = px - fx;
        int y0 = (int)fy, x0 = (int)fx;
        float hy = 1.f - ly, hx = 1.f - lx;
        float w00 = hy * hx * m, w01 = hy * lx * m;
        float w10 = ly * hx * m, w11 = ly * lx * m;
        bool vy0 = (unsigned)y0 < 64u;
        bool vy1 = (unsigned)(y0 + 1) < 64u;
        bool vx0 = (unsigned)x0 < 64u;
        bool vx1 = (unsigned)(x0 + 1) < 64u;
        if (!(vy0 && vx0)) w00 = 0.f;
        if (!(vy0 && vx1)) w01 = 0.f;
        if (!(vy1 && vx0)) w10 = 0.f;
        if (!(vy1 && vx1)) w11 = 0.f;
        int y0a = min(max(y0, 0), 63), y1a = min(max(y0 + 1, 0), 63);
        int x0a = min(max(x0, 0), 63), x1a = min(max(x0 + 1, 0), 63);
        g_wt[bh * 576 + i] = make_float4(w00, w01, w10, w11);
        g_offp[bh * 576 + i] =
            make_ushort4((unsigned short)(y0a * 64 + x0a),
                         (unsigned short)(y0a * 64 + x1a),
                         (unsigned short)(y1a * 64 + x0a),
                         (unsigned short)(y1a * 64 + x1a));
    }
}

// ============================================================================
// Kernel 2: fused deformable sampling + mma.sync GEMM + BN + SiLU, with the
// gather software-pipelined across the MMA blocks. (proven R8, unchanged)
// ============================================================================
#define SM_WT  98304    // float4[576]
#define SM_OFF 107520   // ushort4[576]
#define SM_SC  112128   // float[128]
#define SM_SH  112640   // float[128]
#define SM2_BYTES 113152

__device__ __forceinline__ void issueA(
    float* pf, const float* __restrict__ xb,
    const ushort4* __restrict__ s_off, int k0, int grp, int tid)
{
#pragma unroll
    for (int j = 0; j < 2; j++) {
        int id = (grp * 2 + j) * 256 + tid;
        int m = (id & 7) | (((id >> 5) & 7) << 3);
        int kp = ((id >> 3) & 3) | ((id >> 8) << 2);
        int k = k0 + kp * 2;
#pragma unroll
        for (int s2 = 0; s2 < 2; s2++) {
            int kk = k + s2;
            unsigned c = (unsigned)kk / 9u;
            int t = kk - c * 9;
            ushort4 o = s_off[t * 64 + m];
            const float* xp = xb + c * 4096;
            float* p = pf + (j * 2 + s2) * 4;
            p[0] = xp[o.x];
            p[1] = xp[o.y];
            p[2] = xp[o.z];
            p[3] = xp[o.w];
        }
    }
}

__device__ __forceinline__ void consumeA(
    char* buf, const float* pf,
    const float4* __restrict__ s_wt, int k0, int grp, int tid)
{
    char* alo = buf + 8192;
#pragma unroll
    for (int j = 0; j < 2; j++) {
        int id = (grp * 2 + j) * 256 + tid;
        int m = (id & 7) | (((id >> 5) & 7) << 3);
        int kp = ((id >> 3) & 3) | ((id >> 8) << 2);
        int k = k0 + kp * 2;
        float v[2];
#pragma unroll
        for (int s2 = 0; s2 < 2; s2++) {
            int kk = k + s2;
            unsigned c = (unsigned)kk / 9u;
            int t = kk - c * 9;
            float4 w = s_wt[t * 64 + m];
            const float* p = pf + (j * 2 + s2) * 4;
            v[s2] = w.x * p[0] + w.y * p[1] + w.z * p[2] + w.w * p[3];
        }
        uint32_t lw, hw = bf16split_hi(v[0], v[1], lw);
        uint32_t off = SWZ128((uint32_t)(m * 128 + kp * 4));
        *(uint32_t*)(buf + off) = hw;
        *(uint32_t*)(alo + off) = lw;
    }
}

__global__ __launch_bounds__(256, 2) void k2_deform_mma(
    const float* __restrict__ x,
    const float* __restrict__ gamma, const float* __restrict__ beta,
    const float* __restrict__ mean, const float* __restrict__ var,
    float* __restrict__ out)
{
    extern __shared__ char sm[];
    const uint32_t sb = smem_u32(sm);
    const int tid = threadIdx.x;
    const int wid = tid >> 5, lid = tid & 31;
    const int blk = blockIdx.x;
    const int b = blk >> 6;
    const int h = blk & 63;

    float4* s_wt = (float4*)(sm + SM_WT);
    ushort4* s_off = (ushort4*)(sm + SM_OFF);
    float* s_sc = (float*)(sm + SM_SC);
    float* s_sh = (float*)(sm + SM_SH);

    const int mbase = (b * 64 + h) * 576;
    for (int i = tid; i < 576; i += 256) {
        s_wt[i] = g_wt[mbase + i];
        s_off[i] = g_offp[mbase + i];
    }
    if (tid < 128) {
        float sc = gamma[tid] * rsqrtf(var[tid] + 1e-5f);
        s_sc[tid] = sc;
        s_sh[tid] = beta[tid] - mean[tid] * sc;
    }
    const float* xb = x + b * CC * HH * WW;
    __syncthreads();

    const int wM = (wid & 1) * 32;
    const int wN = (wid >> 1) * 32;
    const int a_row = lid & 15;
    const int a_col = (lid >> 4) * 8;
    const int b_row = (lid & 7) + ((lid >> 4) << 3);
    const int b_col = ((lid >> 3) & 1) * 8;

    float acc[2][4][4];
#pragma unroll
    for (int mt = 0; mt < 2; mt++)
#pragma unroll
        for (int nt = 0; nt < 4; nt++)
#pragma unroll
            for (int i = 0; i < 4; i++) acc[mt][nt][i] = 0.f;

    float pf[16];

    // prologue: stage chunk 0 into buf 0
    {
        uint32_t bsm = sb + 16384;
#pragma unroll
        for (int it = 0; it < 8; it++) {
            int ln = it * 256 + tid;
            cp_async16(bsm + ln * 16, g_wb + ln * 16);
        }
        cp_commit();
#pragma unroll
        for (int g = 0; g < 4; g++) {
            issueA(pf, xb, s_off, 0, g, tid);
            consumeA(sm, pf, s_wt, 0, g, tid);
        }
        cp_wait0();
    }
    __syncthreads();

    for (int ch = 0; ch < 18; ch++) {
        const int cur = ch & 1;
        const uint32_t baseA = sb + cur * 49152;
        char* nxt = sm + (cur ^ 1) * 49152;
        const int kn = (ch + 1) * 64;
        const bool more = (ch < 17);

        if (more) {
            uint32_t bsm = sb + (cur ^ 1) * 49152 + 16384;
            const char* gsrc = g_wb + (ch + 1) * 32768;
#pragma unroll
            for (int it = 0; it < 8; it++) {
                int ln = it * 256 + tid;
                cp_async16(bsm + ln * 16, gsrc + ln * 16);
            }
            cp_commit();
            issueA(pf, xb, s_off, kn, 0, tid);
        }

#pragma unroll
        for (int ks = 0; ks < 4; ks++) {
            uint32_t ah[2][4], al[2][4];
#pragma unroll
            for (int mt = 0; mt < 2; mt++) {
                uint32_t off = SWZ128((uint32_t)((wM + mt * 16 + a_row) * 128 +
                                                 (ks * 16 + a_col) * 2));
                ldsm_x4(ah[mt], baseA + off);
                ldsm_x4(al[mt], baseA + 8192 + off);
            }
            uint32_t bhf[2][4], blf[2][4];
#pragma unroll
            for (int p = 0; p < 2; p++) {
                uint32_t off = SWZ128((uint32_t)((wN + p * 16 + b_row) * 128 +
                                                 (ks * 16 + b_col) * 2));
                ldsm_x4(bhf[p], baseA + 16384 + off);
                ldsm_x4(blf[p], baseA + 32768 + off);
            }
#pragma unroll
            for (int mt = 0; mt < 2; mt++)
#pragma unroll
                for (int nt = 0; nt < 4; nt++) {
                    const uint32_t* bhp = &bhf[nt >> 1][(nt & 1) * 2];
                    const uint32_t* blp = &blf[nt >> 1][(nt & 1) * 2];
                    mma_bf16(acc[mt][nt], ah[mt], bhp);
                    mma_bf16(acc[mt][nt], ah[mt], blp);
                    mma_bf16(acc[mt][nt], al[mt], bhp);
                }

            if (more) {
                consumeA(nxt, pf, s_wt, kn, ks, tid);
                if (ks < 3) issueA(pf, xb, s_off, kn, ks + 1, tid);
            }
        }

        cp_wait0();
        __syncthreads();
    }

    // epilogue: BN + SiLU + store
    const int g = lid >> 2, t2 = (lid & 3) * 2;
#pragma unroll
    for (int mt = 0; mt < 2; mt++) {
#pragma unroll
        for (int nt = 0; nt < 4; nt++) {
#pragma unroll
            for (int i = 0; i < 4; i++) {
                int m = wM + mt * 16 + g + ((i >> 1) ? 8 : 0);
                int n = wN + nt * 8 + t2 + (i & 1);
                float v = acc[mt][nt][i] * s_sc[n] + s_sh[n];
                v = v / (1.f + __expf(-v));
                out[((b * OO + n) * HH + h) * WW + m] = v;
            }
        }
    }
}

extern "C" void kernel_launch(void* const* d_in, const int* in_sizes, int n_in,
                              void* d_out, int out_size)
{
    const float* x  = (const float*)d_in[0];
    const float* ow = (const float*)d_in[1];
    const float* ob = (const float*)d_in[2];
    const float* mw = (const float*)d_in[3];
    const float* mb = (const float*)d_in[4];
    const float* wg = (const float*)d_in[5];
    const float* gg = (const float*)d_in[6];
    const float* bt = (const float*)d_in[7];
    const float* mu = (const float*)d_in[8];
    const float* vr = (const float*)d_in[9];
    float* out = (float*)d_out;

    cudaFuncSetAttribute(k1g_conv_mma,
                         cudaFuncAttributeMaxDynamicSharedMemorySize, SMC_BYTES);
    cudaFuncSetAttribute(k2_deform_mma,
                         cudaFuncAttributeMaxDynamicSharedMemorySize, SM2_BYTES);

    k0_prep<<<360, 256>>>(wg, ow, mw);
    k1g_conv_mma<<<128, 256, SMC_BYTES>>>(x);
    k1b_meta<<<256, 256>>>(ob, mb);
    k2_deform_mma<<<BB * HH, 256, SM2_BYTES>>>(x, gg, bt, mu, vr, out);
}

// round 11
// speedup vs baseline: 2.2388x; 1.0776x over previous
#include <cuda_runtime.h>
#include <cuda_bf16.h>
#include <cstdint>

// Problem constants (fixed by setup_inputs)
#define BB 4
#define CC 128
#define HH 64
#define WW 64
#define OO 128
#define TT 9

// Sampling metadata: per (b,h) row: 9 taps x 64 pixels.
__device__ float4  g_wt[BB * HH * TT * WW];   // bilinear weights * mask (0 if invalid)
__device__ ushort4 g_offp[BB * HH * TT * WW]; // clamped flat offsets (y*64+x), 4 corners
// Pre-split, pre-swizzled bf16 GEMM weights: [18 chunks][hi 16KB | lo 16KB]
__device__ __align__(16) char g_wb[18 * 32768];
// Pre-split, pre-swizzled bf16 conv weights (27 oc padded to 32):
// [18 chunks][hi 4KB | lo 4KB]
__device__ __align__(16) char g_wbc[18 * 8192];
// Conv output sums (no bias): [bh][28 oc (27 used)][64 w]
__device__ float g_conv[256 * 28 * 64];

// ---------------------------------------------------------------------------
// helpers
// ---------------------------------------------------------------------------
__device__ __forceinline__ uint32_t smem_u32(const void* p) {
    uint32_t a;
    asm("{ .reg .u64 t; cvta.to.shared.u64 t, %1; cvt.u32.u64 %0, t; }"
        : "=r"(a) : "l"(p));
    return a;
}
#define SWZ128(o) ((o) ^ (((o) >> 3) & 0x70))

__device__ __forceinline__ void ldsm_x4(uint32_t* r, uint32_t addr) {
    asm volatile("ldmatrix.sync.aligned.m8n8.x4.shared.b16 {%0,%1,%2,%3}, [%4];"
                 : "=r"(r[0]), "=r"(r[1]), "=r"(r[2]), "=r"(r[3]) : "r"(addr));
}
__device__ __forceinline__ void mma_bf16(float* c, const uint32_t* a,
                                         const uint32_t* b) {
    asm volatile("mma.sync.aligned.m16n8k16.row.col.f32.bf16.bf16.f32 "
                 "{%0,%1,%2,%3}, {%4,%5,%6,%7}, {%8,%9}, {%0,%1,%2,%3};"
                 : "+f"(c[0]), "+f"(c[1]), "+f"(c[2]), "+f"(c[3])
                 : "r"(a[0]), "r"(a[1]), "r"(a[2]), "r"(a[3]),
                   "r"(b[0]), "r"(b[1]));
}
__device__ __forceinline__ uint32_t bf16split_hi(float v0, float v1, uint32_t& lw) {
    __nv_bfloat16 h0 = __float2bfloat16(v0);
    __nv_bfloat16 h1 = __float2bfloat16(v1);
    __nv_bfloat16 l0 = __float2bfloat16(v0 - __bfloat162float(h0));
    __nv_bfloat16 l1 = __float2bfloat16(v1 - __bfloat162float(h1));
    lw = ((uint32_t)__bfloat16_as_ushort(l1) << 16) | __bfloat16_as_ushort(l0);
    return ((uint32_t)__bfloat16_as_ushort(h1) << 16) | __bfloat16_as_ushort(h0);
}
__device__ __forceinline__ void cp_async16(uint32_t smem_dst, const void* gsrc) {
    asm volatile("cp.async.cg.shared.global [%0], [%1], 16;"
                 :: "r"(smem_dst), "l"(gsrc) : "memory");
}
__device__ __forceinline__ void cp_commit() {
    asm volatile("cp.async.commit_group;" ::: "memory");
}
__device__ __forceinline__ void cp_wait0() {
    asm volatile("cp.async.wait_group 0;" ::: "memory");
}

// ============================================================================
// Kernel 0: weight prep. CTAs 0..287: GEMM weights -> g_wb.
// CTAs 288..359: conv weights (27 oc padded to 32) -> g_wbc.
// ============================================================================
__global__ __launch_bounds__(256) void k0_prep(
    const float* __restrict__ wgt,
    const float* __restrict__ ow, const float* __restrict__ mw)
{
    const int blk = blockIdx.x;
    if (blk < 288) {
        int id = blk * 256 + threadIdx.x;  // 73728 items
        int ch = id >> 12;
        int r = id & 4095;
        int o = r >> 5, kp = r & 31;
        float2 wv = *(const float2*)(wgt + o * 1152 + ch * 64 + kp * 2);
        uint32_t lw, hw = bf16split_hi(wv.x, wv.y, lw);
        uint32_t off = SWZ128((uint32_t)(o * 128 + kp * 4));
        *(uint32_t*)(g_wb + ch * 32768 + off) = hw;
        *(uint32_t*)(g_wb + ch * 32768 + 16384 + off) = lw;
    } else {
        int id = (blk - 288) * 256 + threadIdx.x;  // 18432 items
        int ch = id >> 10;
        int r = id & 1023;
        int oc = r >> 5, kp = r & 31;
        int k = ch * 64 + kp * 2;
        float v0 = 0.f, v1 = 0.f;
        if (oc < 18) {
            v0 = ow[oc * 1152 + k];
            v1 = ow[oc * 1152 + k + 1];
        } else if (oc < 27) {
            v0 = mw[(oc - 18) * 1152 + k];
            v1 = mw[(oc - 18) * 1152 + k + 1];
        }
        uint32_t lw, hw = bf16split_hi(v0, v1, lw);
        uint32_t off = SWZ128((uint32_t)(oc * 128 + kp * 4));
        *(uint32_t*)(g_wbc + ch * 8192 + off) = hw;
        *(uint32_t*)(g_wbc + ch * 8192 + 4096 + off) = lw;
    }
}

// ============================================================================
// Kernel 1g: 27-channel conv as implicit GEMM (im2col, gather-free staging).
// grid = 128 (2 image rows, M=128), block = 256 (8 warps, warp M32 x N16).
// Staging map is warp-coherent: each LDG instruction = 32 consecutive pixels
// of one (channel, tap).
// ============================================================================
#define CSTG 40960
#define SMC_BYTES (2 * CSTG)

__device__ __forceinline__ void stage_Ac(
    char* buf, const float* __restrict__ xb, int h0, int k0, int wid, int lane)
{
    char* alo = buf + 16384;
#pragma unroll 4
    for (int it = 0; it < 16; it++) {
        int c2 = it * 8 + wid;          // 0..127
        int kp = c2 >> 2;               // 0..31
        int m = (c2 & 3) * 32 + lane;   // 0..127
        int k = k0 + kp * 2;
        float v[2];
#pragma unroll
        for (int s2 = 0; s2 < 2; s2++) {
            int kk = k + s2;
            unsigned c = (unsigned)kk / 9u;
            int t = kk - c * 9;
            int ii = t / 3;
            int jj = t - ii * 3;
            int y = h0 + (m >> 6) + ii - 1;
            int xw = (m & 63) + jj - 1;
            bool valid = ((unsigned)y < 64u) && ((unsigned)xw < 64u);
            v[s2] = valid ? xb[c * 4096 + y * 64 + xw] : 0.f;
        }
        uint32_t lw, hw = bf16split_hi(v[0], v[1], lw);
        uint32_t off = SWZ128((uint32_t)(m * 128 + kp * 4));
        *(uint32_t*)(buf + off) = hw;
        *(uint32_t*)(alo + off) = lw;
    }
}

__global__ __launch_bounds__(256, 1) void k1g_conv_mma(const float* __restrict__ x)
{
    extern __shared__ char sm[];
    const uint32_t sb = smem_u32(sm);
    const int tid = threadIdx.x;
    const int wid = tid >> 5, lid = tid & 31;
    const int blk = blockIdx.x;
    const int b = blk >> 5;
    const int h0 = (blk & 31) * 2;
    const float* xb = x + b * CC * HH * WW;

    const int wM = (wid & 3) * 32;
    const int wN = (wid >> 2) * 16;
    const int a_row = lid & 15;
    const int a_col = (lid >> 4) * 8;
    const int b_row = (lid & 7) + ((lid >> 4) << 3);
    const int b_col = ((lid >> 3) & 1) * 8;

    float acc[2][2][4];
#pragma unroll
    for (int mt = 0; mt < 2; mt++)
#pragma unroll
        for (int nt = 0; nt < 2; nt++)
#pragma unroll
            for (int i = 0; i < 4; i++) acc[mt][nt][i] = 0.f;

    // prologue: stage chunk 0 into buf 0
    {
        uint32_t bsm = sb + 32768;
#pragma unroll
        for (int it = 0; it < 2; it++) {
            int ln = it * 256 + tid;
            cp_async16(bsm + ln * 16, g_wbc + ln * 16);
        }
        cp_commit();
        stage_Ac(sm, xb, h0, 0, wid, lid);
        cp_wait0();
    }
    __syncthreads();

    for (int ch = 0; ch < 18; ch++) {
        const int cur = ch & 1;
        const uint32_t baseA = sb + cur * CSTG;
        char* nxt = sm + (cur ^ 1) * CSTG;

        if (ch < 17) {
            uint32_t bsm = sb + (cur ^ 1) * CSTG + 32768;
            const char* gsrc = g_wbc + (ch + 1) * 8192;
#pragma unroll
            for (int it = 0; it < 2; it++) {
                int ln = it * 256 + tid;
                cp_async16(bsm + ln * 16, gsrc + ln * 16);
            }
            cp_commit();
        }

#pragma unroll
        for (int ks = 0; ks < 4; ks++) {
            uint32_t bhf[4], blf[4];
            {
                uint32_t off = SWZ128((uint32_t)((wN + b_row) * 128 +
                                                 (ks * 16 + b_col) * 2));
                ldsm_x4(bhf, baseA + 32768 + off);
                ldsm_x4(blf, baseA + 36864 + off);
            }
#pragma unroll
            for (int mt = 0; mt < 2; mt++) {
                uint32_t ah[4], al[4];
                uint32_t off = SWZ128((uint32_t)((wM + mt * 16 + a_row) * 128 +
                                                 (ks * 16 + a_col) * 2));
                ldsm_x4(ah, baseA + off);
                ldsm_x4(al, baseA + 16384 + off);
#pragma unroll
                for (int nt = 0; nt < 2; nt++) {
                    const uint32_t* bhp = &bhf[nt * 2];
                    const uint32_t* blp = &blf[nt * 2];
                    mma_bf16(acc[mt][nt], ah, bhp);
                    mma_bf16(acc[mt][nt], ah, blp);
                    mma_bf16(acc[mt][nt], al, bhp);
                }
            }
        }

        if (ch < 17) stage_Ac(nxt, xb, h0, (ch + 1) * 64, wid, lid);
        cp_wait0();
        __syncthreads();
    }

    // epilogue: write fp32 conv sums
    const int g = lid >> 2, t2 = (lid & 3) * 2;
#pragma unroll
    for (int mt = 0; mt < 2; mt++) {
#pragma unroll
        for (int nt = 0; nt < 2; nt++) {
#pragma unroll
            for (int i = 0; i < 4; i++) {
                int n = wN + nt * 8 + t2 + (i & 1);
                if (n >= 27) continue;
                int m = wM + mt * 16 + g + ((i >> 1) ? 8 : 0);
                int hh = h0 + (m >> 6), w = m & 63;
                g_conv[(b * 64 + hh) * 1792 + n * 64 + w] = acc[mt][nt][i];
            }
        }
    }
}

// ============================================================================
// Kernel 1b: bias + sigmoid + bilinear sampling metadata from g_conv.
// ============================================================================
__global__ __launch_bounds__(256) void k1b_meta(
    const float* __restrict__ ob, const float* __restrict__ mb)
{
    const int bh = blockIdx.x;
    const int h = bh & 63;
    const int tid = threadIdx.x;
    const float* gp = g_conv + bh * 1792;

    for (int i = tid; i < TT * 64; i += 256) {
        int t = i >> 6, ww = i & 63;
        float s0 = gp[(2 * t) * 64 + ww];
        float s1 = gp[(2 * t + 1) * 64 + ww];
        float s2 = gp[(18 + t) * 64 + ww];
        float offy = s0 + ob[2 * t];
        float offx = s1 + ob[2 * t + 1];
        float m = 1.f / (1.f + __expf(-(s2 + mb[t])));

        int ii = t / 3;
        int jj = t - ii * 3;
        float py = (float)(h - 1 + ii) + offy;
        float px = (float)(ww - 1 + jj) + offx;
        float fy = floorf(py), fx = floorf(px);
        float ly = py - fy, lx = px - fx;
        int y0 = (int)fy, x0 = (int)fx;
        float hy = 1.f - ly, hx = 1.f - lx;
        float w00 = hy * hx * m, w01 = hy * lx * m;
        float w10 = ly * hx * m, w11 = ly * lx * m;
        bool vy0 = (unsigned)y0 < 64u;
        bool vy1 = (unsigned)(y0 + 1) < 64u;
        bool vx0 = (unsigned)x0 < 64u;
        bool vx1 = (unsigned)(x0 + 1) < 64u;
        if (!(vy0 && vx0)) w00 = 0.f;
        if (!(vy0 && vx1)) w01 = 0.f;
        if (!(vy1 && vx0)) w10 = 0.f;
        if (!(vy1 && vx1)) w11 = 0.f;
        int y0a = min(max(y0, 0), 63), y1a = min(max(y0 + 1, 0), 63);
        int x0a = min(max(x0, 0), 63), x1a = min(max(x0 + 1, 0), 63);
        g_wt[bh * 576 + i] = make_float4(w00, w01, w10, w11);
        g_offp[bh * 576 + i] =
            make_ushort4((unsigned short)(y0a * 64 + x0a),
                         (unsigned short)(y0a * 64 + x1a),
                         (unsigned short)(y1a * 64 + x0a),
                         (unsigned short)(y1a * 64 + x1a));
    }
}

// ============================================================================
// Kernel 2: fused deformable sampling + mma.sync GEMM + BN + SiLU, gather
// software-pipelined across MMA blocks, warp-coherent gather map:
// each LDG instruction = one (channel, tap) x 32 consecutive pixels.
// ============================================================================
#define SM_WT  98304    // float4[576]
#define SM_OFF 107520   // ushort4[576]
#define SM_SC  112128   // float[128]
#define SM_SH  112640   // float[128]
#define SM2_BYTES 113152

__device__ __forceinline__ void issueA(
    float* pf, const float* __restrict__ xb,
    const ushort4* __restrict__ s_off, int k0, int grp, int wid, int lane)
{
#pragma unroll
    for (int j = 0; j < 2; j++) {
        int c2 = (grp * 2 + j) * 8 + wid;   // 0..63
        int kp = c2 >> 1;                   // 0..31
        int m = (c2 & 1) * 32 + lane;       // 0..63
        int k = k0 + kp * 2;
#pragma unroll
        for (int s2 = 0; s2 < 2; s2++) {
            int kk = k + s2;
            unsigned c = (unsigned)kk / 9u;
            int t = kk - c * 9;
            ushort4 o = s_off[t * 64 + m];
            const float* xp = xb + c * 4096;
            float* p = pf + (j * 2 + s2) * 4;
            p[0] = xp[o.x];
            p[1] = xp[o.y];
            p[2] = xp[o.z];
            p[3] = xp[o.w];
        }
    }
}

__device__ __forceinline__ void consumeA(
    char* buf, const float* pf,
    const float4* __restrict__ s_wt, int k0, int grp, int wid, int lane)
{
    char* alo = buf + 8192;
#pragma unroll
    for (int j = 0; j < 2; j++) {
        int c2 = (grp * 2 + j) * 8 + wid;
        int kp = c2 >> 1;
        int m = (c2 & 1) * 32 + lane;
        int k = k0 + kp * 2;
        float v[2];
#pragma unroll
        for (int s2 = 0; s2 < 2; s2++) {
            int kk = k + s2;
            unsigned c = (unsigned)kk / 9u;
            int t = kk - c * 9;
            float4 w = s_wt[t * 64 + m];
            const float* p = pf + (j * 2 + s2) * 4;
            v[s2] = w.x * p[0] + w.y * p[1] + w.z * p[2] + w.w * p[3];
        }
        uint32_t lw, hw = bf16split_hi(v[0], v[1], lw);
        uint32_t off = SWZ128((uint32_t)(m * 128 + kp * 4));
        *(uint32_t*)(buf + off) = hw;
        *(uint32_t*)(alo + off) = lw;
    }
}

__global__ __launch_bounds__(256, 2) void k2_deform_mma(
    const float* __restrict__ x,
    const float* __restrict__ gamma, const float* __restrict__ beta,
    const float* __restrict__ mean, const float* __restrict__ var,
    float* __restrict__ out)
{
    extern __shared__ char sm[];
    const uint32_t sb = smem_u32(sm);
    const int tid = threadIdx.x;
    const int wid = tid >> 5, lid = tid & 31;
    const int blk = blockIdx.x;
    const int b = blk >> 6;
    const int h = blk & 63;

    float4* s_wt = (float4*)(sm + SM_WT);
    ushort4* s_off = (ushort4*)(sm + SM_OFF);
    float* s_sc = (float*)(sm + SM_SC);
    float* s_sh = (float*)(sm + SM_SH);

    const int mbase = (b * 64 + h) * 576;
    for (int i = tid; i < 576; i += 256) {
        s_wt[i] = g_wt[mbase + i];
        s_off[i] = g_offp[mbase + i];
    }
    if (tid < 128) {
        float sc = gamma[tid] * rsqrtf(var[tid] + 1e-5f);
        s_sc[tid] = sc;
        s_sh[tid] = beta[tid] - mean[tid] * sc;
    }
    const float* xb = x + b * CC * HH * WW;
    __syncthreads();

    const int wM = (wid & 1) * 32;
    const int wN = (wid >> 1) * 32;
    const int a_row = lid & 15;
    const int a_col = (lid >> 4) * 8;
    const int b_row = (lid & 7) + ((lid >> 4) << 3);
    const int b_col = ((lid >> 3) & 1) * 8;

    float acc[2][4][4];
#pragma unroll
    for (int mt = 0; mt < 2; mt++)
#pragma unroll
        for (int nt = 0; nt < 4; nt++)
#pragma unroll
            for (int i = 0; i < 4; i++) acc[mt][nt][i] = 0.f;

    float pf[16];

    // prologue: stage chunk 0 into buf 0
    {
        uint32_t bsm = sb + 16384;
#pragma unroll
        for (int it = 0; it < 8; it++) {
            int ln = it * 256 + tid;
            cp_async16(bsm + ln * 16, g_wb + ln * 16);
        }
        cp_commit();
#pragma unroll
        for (int g = 0; g < 4; g++) {
            issueA(pf, xb, s_off, 0, g, wid, lid);
            consumeA(sm, pf, s_wt, 0, g, wid, lid);
        }
        cp_wait0();
    }
    __syncthreads();

    for (int ch = 0; ch < 18; ch++) {
        const int cur = ch & 1;
        const uint32_t baseA = sb + cur * 49152;
        char* nxt = sm + (cur ^ 1) * 49152;
        const int kn = (ch + 1) * 64;
        const bool more = (ch < 17);

        if (more) {
            uint32_t bsm = sb + (cur ^ 1) * 49152 + 16384;
            const char* gsrc = g_wb + (ch + 1) * 32768;
#pragma unroll
            for (int it = 0; it < 8; it++) {
                int ln = it * 256 + tid;
                cp_async16(bsm + ln * 16, gsrc + ln * 16);
            }
            cp_commit();
            issueA(pf, xb, s_off, kn, 0, wid, lid);
        }

#pragma unroll
        for (int ks = 0; ks < 4; ks++) {
            uint32_t ah[2][4], al[2][4];
#pragma unroll
            for (int mt = 0; mt < 2; mt++) {
                uint32_t off = SWZ128((uint32_t)((wM + mt * 16 + a_row) * 128 +
                                                 (ks * 16 + a_col) * 2));
                ldsm_x4(ah[mt], baseA + off);
                ldsm_x4(al[mt], baseA + 8192 + off);
            }
            uint32_t bhf[2][4], blf[2][4];
#pragma unroll
            for (int p = 0; p < 2; p++) {
                uint32_t off = SWZ128((uint32_t)((wN + p * 16 + b_row) * 128 +
                                                 (ks * 16 + b_col) * 2));
                ldsm_x4(bhf[p], baseA + 16384 + off);
                ldsm_x4(blf[p], baseA + 32768 + off);
            }
#pragma unroll
            for (int mt = 0; mt < 2; mt++)
#pragma unroll
                for (int nt = 0; nt < 4; nt++) {
                    const uint32_t* bhp = &bhf[nt >> 1][(nt & 1) * 2];
                    const uint32_t* blp = &blf[nt >> 1][(nt & 1) * 2];
                    mma_bf16(acc[mt][nt], ah[mt], bhp);
                    mma_bf16(acc[mt][nt], ah[mt], blp);
                    mma_bf16(acc[mt][nt], al[mt], bhp);
                }

            if (more) {
                consumeA(nxt, pf, s_wt, kn, ks, wid, lid);
                if (ks < 3) issueA(pf, xb, s_off, kn, ks + 1, wid, lid);
            }
        }

        cp_wait0();
        __syncthreads();
    }

    // epilogue: BN + SiLU + store
    const int g = lid >> 2, t2 = (lid & 3) * 2;
#pragma unroll
    for (int mt = 0; mt < 2; mt++) {
#pragma unroll
        for (int nt = 0; nt < 4; nt++) {
#pragma unroll
            for (int i = 0; i < 4; i++) {
                int m = wM + mt * 16 + g + ((i >> 1) ? 8 : 0);
                int n = wN + nt * 8 + t2 + (i & 1);
                float v = acc[mt][nt][i] * s_sc[n] + s_sh[n];
                v = v / (1.f + __expf(-v));
                out[((b * OO + n) * HH + h) * WW + m] = v;
            }
        }
    }
}

extern "C" void kernel_launch(void* const* d_in, const int* in_sizes, int n_in,
                              void* d_out, int out_size)
{
    const float* x  = (const float*)d_in[0];
    const float* ow = (const float*)d_in[1];
    const float* ob = (const float*)d_in[2];
    const float* mw = (const float*)d_in[3];
    const float* mb = (const float*)d_in[4];
    const float* wg = (const float*)d_in[5];
    const float* gg = (const float*)d_in[6];
    const float* bt = (const float*)d_in[7];
    const float* mu = (const float*)d_in[8];
    const float* vr = (const float*)d_in[9];
    float* out = (float*)d_out;

    cudaFuncSetAttribute(k1g_conv_mma,
                         cudaFuncAttributeMaxDynamicSharedMemorySize, SMC_BYTES);
    cudaFuncSetAttribute(k2_deform_mma,
                         cudaFuncAttributeMaxDynamicSharedMemorySize, SM2_BYTES);

    k0_prep<<<360, 256>>>(wg, ow, mw);
    k1g_conv_mma<<<128, 256, SMC_BYTES>>>(x);
    k1b_meta<<<256, 256>>>(ob, mb);
    k2_deform_mma<<<BB * HH, 256, SM2_BYTES>>>(x, gg, bt, mu, vr, out);
}

// round 12
// speedup vs baseline: 2.9502x; 1.3178x over previous
#include <cuda_runtime.h>
#include <cuda_fp16.h>
#include <cstdint>

// Problem constants (fixed by setup_inputs)
#define BB 4
#define CC 128
#define HH 64
#define WW 64
#define OO 128
#define TT 9

// Sampling metadata: per (b,h) row: 9 taps x 64 pixels.
__device__ float4  g_wt[BB * HH * TT * WW];   // bilinear weights * mask (0 if invalid)
__device__ ushort4 g_offp[BB * HH * TT * WW]; // clamped flat offsets (y*64+x), 4 corners
// Pre-converted, pre-swizzled fp16 GEMM weights: [18 chunks][16KB]
__device__ __align__(16) char g_wb[18 * 16384];
// Pre-converted, pre-swizzled fp16 conv weights (27 oc padded to 32): [18][4KB]
__device__ __align__(16) char g_wbc[18 * 4096];
// Conv output sums (no bias): [bh][28 oc (27 used)][64 w]
__device__ float g_conv[256 * 28 * 64];

// ---------------------------------------------------------------------------
// helpers
// ---------------------------------------------------------------------------
__device__ __forceinline__ uint32_t smem_u32(const void* p) {
    uint32_t a;
    asm("{ .reg .u64 t; cvta.to.shared.u64 t, %1; cvt.u32.u64 %0, t; }"
        : "=r"(a) : "l"(p));
    return a;
}
#define SWZ128(o) ((o) ^ (((o) >> 3) & 0x70))

__device__ __forceinline__ void ldsm_x4(uint32_t* r, uint32_t addr) {
    asm volatile("ldmatrix.sync.aligned.m8n8.x4.shared.b16 {%0,%1,%2,%3}, [%4];"
                 : "=r"(r[0]), "=r"(r[1]), "=r"(r[2]), "=r"(r[3]) : "r"(addr));
}
__device__ __forceinline__ void mma_f16(float* c, const uint32_t* a,
                                        const uint32_t* b) {
    asm volatile("mma.sync.aligned.m16n8k16.row.col.f32.f16.f16.f32 "
                 "{%0,%1,%2,%3}, {%4,%5,%6,%7}, {%8,%9}, {%0,%1,%2,%3};"
                 : "+f"(c[0]), "+f"(c[1]), "+f"(c[2]), "+f"(c[3])
                 : "r"(a[0]), "r"(a[1]), "r"(a[2]), "r"(a[3]),
                   "r"(b[0]), "r"(b[1]));
}
__device__ __forceinline__ uint32_t fp16pack(float v0, float v1) {
    __half2 h = __floats2half2_rn(v0, v1);
    uint32_t r;
    *(__half2*)&r = h;
    return r;
}
__device__ __forceinline__ void cp_async16(uint32_t smem_dst, const void* gsrc) {
    asm volatile("cp.async.cg.shared.global [%0], [%1], 16;"
                 :: "r"(smem_dst), "l"(gsrc) : "memory");
}
__device__ __forceinline__ void cp_commit() {
    asm volatile("cp.async.commit_group;" ::: "memory");
}
__device__ __forceinline__ void cp_wait0() {
    asm volatile("cp.async.wait_group 0;" ::: "memory");
}

// ============================================================================
// Kernel 0: weight prep (fp16, pre-swizzled). CTAs 0..287: GEMM -> g_wb.
// CTAs 288..359: conv weights (27 oc padded to 32) -> g_wbc.
// ============================================================================
__global__ __launch_bounds__(256) void k0_prep(
    const float* __restrict__ wgt,
    const float* __restrict__ ow, const float* __restrict__ mw)
{
    const int blk = blockIdx.x;
    if (blk < 288) {
        int id = blk * 256 + threadIdx.x;  // 73728 items
        int ch = id >> 12;
        int r = id & 4095;
        int o = r >> 5, kp = r & 31;
        float2 wv = *(const float2*)(wgt + o * 1152 + ch * 64 + kp * 2);
        uint32_t off = SWZ128((uint32_t)(o * 128 + kp * 4));
        *(uint32_t*)(g_wb + ch * 16384 + off) = fp16pack(wv.x, wv.y);
    } else {
        int id = (blk - 288) * 256 + threadIdx.x;  // 18432 items
        int ch = id >> 10;
        int r = id & 1023;
        int oc = r >> 5, kp = r & 31;
        int k = ch * 64 + kp * 2;
        float v0 = 0.f, v1 = 0.f;
        if (oc < 18) {
            v0 = ow[oc * 1152 + k];
            v1 = ow[oc * 1152 + k + 1];
        } else if (oc < 27) {
            v0 = mw[(oc - 18) * 1152 + k];
            v1 = mw[(oc - 18) * 1152 + k + 1];
        }
        uint32_t off = SWZ128((uint32_t)(oc * 128 + kp * 4));
        *(uint32_t*)(g_wbc + ch * 4096 + off) = fp16pack(v0, v1);
    }
}

// ============================================================================
// Kernel 1g: 27-channel conv as implicit GEMM (im2col, fp16 single-pass).
// grid = 128 (2 image rows, M=128), block = 256 (8 warps, warp M32 x N16).
// Stage = A 16KB | B 4KB = 20KB, double-buffered.
// ============================================================================
#define CSTG 20480
#define SMC_BYTES (2 * CSTG)

__device__ __forceinline__ void stage_Ac(
    char* buf, const float* __restrict__ xb, int h0, int k0, int wid, int lane)
{
#pragma unroll 4
    for (int it = 0; it < 16; it++) {
        int c2 = it * 8 + wid;          // 0..127
        int kp = c2 >> 2;               // 0..31
        int m = (c2 & 3) * 32 + lane;   // 0..127
        int k = k0 + kp * 2;
        float v[2];
#pragma unroll
        for (int s2 = 0; s2 < 2; s2++) {
            int kk = k + s2;
            unsigned c = (unsigned)kk / 9u;
            int t = kk - c * 9;
            int ii = t / 3;
            int jj = t - ii * 3;
            int y = h0 + (m >> 6) + ii - 1;
            int xw = (m & 63) + jj - 1;
            bool valid = ((unsigned)y < 64u) && ((unsigned)xw < 64u);
            v[s2] = valid ? xb[c * 4096 + y * 64 + xw] : 0.f;
        }
        uint32_t off = SWZ128((uint32_t)(m * 128 + kp * 4));
        *(uint32_t*)(buf + off) = fp16pack(v[0], v[1]);
    }
}

__global__ __launch_bounds__(256, 1) void k1g_conv_mma(const float* __restrict__ x)
{
    extern __shared__ char sm[];
    const uint32_t sb = smem_u32(sm);
    const int tid = threadIdx.x;
    const int wid = tid >> 5, lid = tid & 31;
    const int blk = blockIdx.x;
    const int b = blk >> 5;
    const int h0 = (blk & 31) * 2;
    const float* xb = x + b * CC * HH * WW;

    const int wM = (wid & 3) * 32;
    const int wN = (wid >> 2) * 16;
    const int a_row = lid & 15;
    const int a_col = (lid >> 4) * 8;
    const int b_row = (lid & 7) + ((lid >> 4) << 3);
    const int b_col = ((lid >> 3) & 1) * 8;

    float acc[2][2][4];
#pragma unroll
    for (int mt = 0; mt < 2; mt++)
#pragma unroll
        for (int nt = 0; nt < 2; nt++)
#pragma unroll
            for (int i = 0; i < 4; i++) acc[mt][nt][i] = 0.f;

    // prologue: stage chunk 0 into buf 0
    {
        uint32_t bsm = sb + 16384;
        cp_async16(bsm + tid * 16, g_wbc + tid * 16);
        cp_commit();
        stage_Ac(sm, xb, h0, 0, wid, lid);
        cp_wait0();
    }
    __syncthreads();

    for (int ch = 0; ch < 18; ch++) {
        const int cur = ch & 1;
        const uint32_t baseA = sb + cur * CSTG;
        char* nxt = sm + (cur ^ 1) * CSTG;

        if (ch < 17) {
            uint32_t bsm = sb + (cur ^ 1) * CSTG + 16384;
            cp_async16(bsm + tid * 16, g_wbc + (ch + 1) * 4096 + tid * 16);
            cp_commit();
        }

#pragma unroll
        for (int ks = 0; ks < 4; ks++) {
            uint32_t bhf[4];
            {
                uint32_t off = SWZ128((uint32_t)((wN + b_row) * 128 +
                                                 (ks * 16 + b_col) * 2));
                ldsm_x4(bhf, baseA + 16384 + off);
            }
#pragma unroll
            for (int mt = 0; mt < 2; mt++) {
                uint32_t ah[4];
                uint32_t off = SWZ128((uint32_t)((wM + mt * 16 + a_row) * 128 +
                                                 (ks * 16 + a_col) * 2));
                ldsm_x4(ah, baseA + off);
#pragma unroll
                for (int nt = 0; nt < 2; nt++)
                    mma_f16(acc[mt][nt], ah, &bhf[nt * 2]);
            }
        }

        if (ch < 17) stage_Ac(nxt, xb, h0, (ch + 1) * 64, wid, lid);
        cp_wait0();
        __syncthreads();
    }

    // epilogue: write fp32 conv sums
    const int g = lid >> 2, t2 = (lid & 3) * 2;
#pragma unroll
    for (int mt = 0; mt < 2; mt++) {
#pragma unroll
        for (int nt = 0; nt < 2; nt++) {
#pragma unroll
            for (int i = 0; i < 4; i++) {
                int n = wN + nt * 8 + t2 + (i & 1);
                if (n >= 27) continue;
                int m = wM + mt * 16 + g + ((i >> 1) ? 8 : 0);
                int hh = h0 + (m >> 6), w = m & 63;
                g_conv[(b * 64 + hh) * 1792 + n * 64 + w] = acc[mt][nt][i];
            }
        }
    }
}

// ============================================================================
// Kernel 1b: bias + sigmoid + bilinear sampling metadata from g_conv.
// ============================================================================
__global__ __launch_bounds__(256) void k1b_meta(
    const float* __restrict__ ob, const float* __restrict__ mb)
{
    const int bh = blockIdx.x;
    const int h = bh & 63;
    const int tid = threadIdx.x;
    const float* gp = g_conv + bh * 1792;

    for (int i = tid; i < TT * 64; i += 256) {
        int t = i >> 6, ww = i & 63;
        float s0 = gp[(2 * t) * 64 + ww];
        float s1 = gp[(2 * t + 1) * 64 + ww];
        float s2 = gp[(18 + t) * 64 + ww];
        float offy = s0 + ob[2 * t];
        float offx = s1 + ob[2 * t + 1];
        float m = 1.f / (1.f + __expf(-(s2 + mb[t])));

        int ii = t / 3;
        int jj = t - ii * 3;
        float py = (float)(h - 1 + ii) + offy;
        float px = (float)(ww - 1 + jj) + offx;
        float fy = floorf(py), fx = floorf(px);
        float ly = py - fy, lx = px - fx;
        int y0 = (int)fy, x0 = (int)fx;
        float hy = 1.f - ly, hx = 1.f - lx;
        float w00 = hy * hx * m, w01 = hy * lx * m;
        float w10 = ly * hx * m, w11 = ly * lx * m;
        bool vy0 = (unsigned)y0 < 64u;
        bool vy1 = (unsigned)(y0 + 1) < 64u;
        bool vx0 = (unsigned)x0 < 64u;
        bool vx1 = (unsigned)(x0 + 1) < 64u;
        if (!(vy0 && vx0)) w00 = 0.f;
        if (!(vy0 && vx1)) w01 = 0.f;
        if (!(vy1 && vx0)) w10 = 0.f;
        if (!(vy1 && vx1)) w11 = 0.f;
        int y0a = min(max(y0, 0), 63), y1a = min(max(y0 + 1, 0), 63);
        int x0a = min(max(x0, 0), 63), x1a = min(max(x0 + 1, 0), 63);
        g_wt[bh * 576 + i] = make_float4(w00, w01, w10, w11);
        g_offp[bh * 576 + i] =
            make_ushort4((unsigned short)(y0a * 64 + x0a),
                         (unsigned short)(y0a * 64 + x1a),
                         (unsigned short)(y1a * 64 + x0a),
                         (unsigned short)(y1a * 64 + x1a));
    }
}

// ============================================================================
// Kernel 2: fused deformable sampling + fp16 mma.sync GEMM + BN + SiLU.
// grid = 256 rows, block = 256, 2 CTAs/SM. Stage = A 8KB | B 16KB = 24KB,
// double-buffered; gather software-pipelined across MMA blocks, warp-coherent.
// ============================================================================
#define K2STG 24576
#define SM_WT  49152    // float4[576]
#define SM_OFF 58368    // ushort4[576]
#define SM_SC  62976    // float[128]
#define SM_SH  63488    // float[128]
#define SM2_BYTES 64000

__device__ __forceinline__ void issueA(
    float* pf, const float* __restrict__ xb,
    const ushort4* __restrict__ s_off, int k0, int grp, int wid, int lane)
{
#pragma unroll
    for (int j = 0; j < 2; j++) {
        int c2 = (grp * 2 + j) * 8 + wid;   // 0..63
        int kp = c2 >> 1;                   // 0..31
        int m = (c2 & 1) * 32 + lane;       // 0..63
        int k = k0 + kp * 2;
#pragma unroll
        for (int s2 = 0; s2 < 2; s2++) {
            int kk = k + s2;
            unsigned c = (unsigned)kk / 9u;
            int t = kk - c * 9;
            ushort4 o = s_off[t * 64 + m];
            const float* xp = xb + c * 4096;
            float* p = pf + (j * 2 + s2) * 4;
            p[0] = xp[o.x];
            p[1] = xp[o.y];
            p[2] = xp[o.z];
            p[3] = xp[o.w];
        }
    }
}

__device__ __forceinline__ void consumeA(
    char* buf, const float* pf,
    const float4* __restrict__ s_wt, int k0, int grp, int wid, int lane)
{
#pragma unroll
    for (int j = 0; j < 2; j++) {
        int c2 = (grp * 2 + j) * 8 + wid;
        int kp = c2 >> 1;
        int m = (c2 & 1) * 32 + lane;
        int k = k0 + kp * 2;
        float v[2];
#pragma unroll
        for (int s2 = 0; s2 < 2; s2++) {
            int kk = k + s2;
            unsigned c = (unsigned)kk / 9u;
            int t = kk - c * 9;
            float4 w = s_wt[t * 64 + m];
            const float* p = pf + (j * 2 + s2) * 4;
            v[s2] = w.x * p[0] + w.y * p[1] + w.z * p[2] + w.w * p[3];
        }
        uint32_t off = SWZ128((uint32_t)(m * 128 + kp * 4));
        *(uint32_t*)(buf + off) = fp16pack(v[0], v[1]);
    }
}

__global__ __launch_bounds__(256, 2) void k2_deform_mma(
    const float* __restrict__ x,
    const float* __restrict__ gamma, const float* __restrict__ beta,
    const float* __restrict__ mean, const float* __restrict__ var,
    float* __restrict__ out)
{
    extern __shared__ char sm[];
    const uint32_t sb = smem_u32(sm);
    const int tid = threadIdx.x;
    const int wid = tid >> 5, lid = tid & 31;
    const int blk = blockIdx.x;
    const int b = blk >> 6;
    const int h = blk & 63;

    float4* s_wt = (float4*)(sm + SM_WT);
    ushort4* s_off = (ushort4*)(sm + SM_OFF);
    float* s_sc = (float*)(sm + SM_SC);
    float* s_sh = (float*)(sm + SM_SH);

    const int mbase = (b * 64 + h) * 576;
    for (int i = tid; i < 576; i += 256) {
        s_wt[i] = g_wt[mbase + i];
        s_off[i] = g_offp[mbase + i];
    }
    if (tid < 128) {
        float sc = gamma[tid] * rsqrtf(var[tid] + 1e-5f);
        s_sc[tid] = sc;
        s_sh[tid] = beta[tid] - mean[tid] * sc;
    }
    const float* xb = x + b * CC * HH * WW;
    __syncthreads();

    const int wM = (wid & 1) * 32;
    const int wN = (wid >> 1) * 32;
    const int a_row = lid & 15;
    const int a_col = (lid >> 4) * 8;
    const int b_row = (lid & 7) + ((lid >> 4) << 3);
    const int b_col = ((lid >> 3) & 1) * 8;

    float acc[2][4][4];
#pragma unroll
    for (int mt = 0; mt < 2; mt++)
#pragma unroll
        for (int nt = 0; nt < 4; nt++)
#pragma unroll
            for (int i = 0; i < 4; i++) acc[mt][nt][i] = 0.f;

    float pf[16];

    // prologue: stage chunk 0 into buf 0
    {
        uint32_t bsm = sb + 8192;
#pragma unroll
        for (int it = 0; it < 4; it++) {
            int ln = it * 256 + tid;
            cp_async16(bsm + ln * 16, g_wb + ln * 16);
        }
        cp_commit();
#pragma unroll
        for (int g = 0; g < 4; g++) {
            issueA(pf, xb, s_off, 0, g, wid, lid);
            consumeA(sm, pf, s_wt, 0, g, wid, lid);
        }
        cp_wait0();
    }
    __syncthreads();

    for (int ch = 0; ch < 18; ch++) {
        const int cur = ch & 1;
        const uint32_t baseA = sb + cur * K2STG;
        char* nxt = sm + (cur ^ 1) * K2STG;
        const int kn = (ch + 1) * 64;
        const bool more = (ch < 17);

        if (more) {
            uint32_t bsm = sb + (cur ^ 1) * K2STG + 8192;
            const char* gsrc = g_wb + (ch + 1) * 16384;
#pragma unroll
            for (int it = 0; it < 4; it++) {
                int ln = it * 256 + tid;
                cp_async16(bsm + ln * 16, gsrc + ln * 16);
            }
            cp_commit();
            issueA(pf, xb, s_off, kn, 0, wid, lid);
        }

#pragma unroll
        for (int ks = 0; ks < 4; ks++) {
            uint32_t ah[2][4];
#pragma unroll
            for (int mt = 0; mt < 2; mt++) {
                uint32_t off = SWZ128((uint32_t)((wM + mt * 16 + a_row) * 128 +
                                                 (ks * 16 + a_col) * 2));
                ldsm_x4(ah[mt], baseA + off);
            }
            uint32_t bhf[2][4];
#pragma unroll
            for (int p = 0; p < 2; p++) {
                uint32_t off = SWZ128((uint32_t)((wN + p * 16 + b_row) * 128 +
                                                 (ks * 16 + b_col) * 2));
                ldsm_x4(bhf[p], baseA + 8192 + off);
            }
#pragma unroll
            for (int mt = 0; mt < 2; mt++)
#pragma unroll
                for (int nt = 0; nt < 4; nt++)
                    mma_f16(acc[mt][nt], ah[mt], &bhf[nt >> 1][(nt & 1) * 2]);

            if (more) {
                consumeA(nxt, pf, s_wt, kn, ks, wid, lid);
                if (ks < 3) issueA(pf, xb, s_off, kn, ks + 1, wid, lid);
            }
        }

        cp_wait0();
        __syncthreads();
    }

    // epilogue: BN + SiLU + store
    const int g = lid >> 2, t2 = (lid & 3) * 2;
#pragma unroll
    for (int mt = 0; mt < 2; mt++) {
#pragma unroll
        for (int nt = 0; nt < 4; nt++) {
#pragma unroll
            for (int i = 0; i < 4; i++) {
                int m = wM + mt * 16 + g + ((i >> 1) ? 8 : 0);
                int n = wN + nt * 8 + t2 + (i & 1);
                float v = acc[mt][nt][i] * s_sc[n] + s_sh[n];
                v = v / (1.f + __expf(-v));
                out[((b * OO + n) * HH + h) * WW + m] = v;
            }
        }
    }
}

extern "C" void kernel_launch(void* const* d_in, const int* in_sizes, int n_in,
                              void* d_out, int out_size)
{
    const float* x  = (const float*)d_in[0];
    const float* ow = (const float*)d_in[1];
    const float* ob = (const float*)d_in[2];
    const float* mw = (const float*)d_in[3];
    const float* mb = (const float*)d_in[4];
    const float* wg = (const float*)d_in[5];
    const float* gg = (const float*)d_in[6];
    const float* bt = (const float*)d_in[7];
    const float* mu = (const float*)d_in[8];
    const float* vr = (const float*)d_in[9];
    float* out = (float*)d_out;

    cudaFuncSetAttribute(k1g_conv_mma,
                         cudaFuncAttributeMaxDynamicSharedMemorySize, SMC_BYTES);
    cudaFuncSetAttribute(k2_deform_mma,
                         cudaFuncAttributeMaxDynamicSharedMemorySize, SM2_BYTES);

    k0_prep<<<360, 256>>>(wg, ow, mw);
    k1g_conv_mma<<<128, 256, SMC_BYTES>>>(x);
    k1b_meta<<<256, 256>>>(ob, mb);
    k2_deform_mma<<<BB * HH, 256, SM2_BYTES>>>(x, gg, bt, mu, vr, out);
}

// round 13
// speedup vs baseline: 3.1978x; 1.0839x over previous
#include <cuda_runtime.h>
#include <cuda_fp16.h>
#include <cstdint>

// Problem constants (fixed by setup_inputs)
#define BB 4
#define CC 128
#define HH 64
#define WW 64
#define OO 128
#define TT 9

// Sampling metadata: per (b,h) row: 9 taps x 64 pixels.
__device__ float4  g_wt[BB * HH * TT * WW];   // bilinear weights * mask (0 if invalid)
__device__ ushort4 g_offp[BB * HH * TT * WW]; // clamped flat offsets (y*64+x), 4 corners
// Pre-converted, pre-swizzled fp16 GEMM weights: [18 chunks][16KB]
__device__ __align__(16) char g_wb[18 * 16384];
// Pre-converted, pre-swizzled fp16 conv weights (27 oc padded to 32): [18][4KB]
__device__ __align__(16) char g_wbc[18 * 4096];

// ---------------------------------------------------------------------------
// helpers
// ---------------------------------------------------------------------------
__device__ __forceinline__ uint32_t smem_u32(const void* p) {
    uint32_t a;
    asm("{ .reg .u64 t; cvta.to.shared.u64 t, %1; cvt.u32.u64 %0, t; }"
        : "=r"(a) : "l"(p));
    return a;
}
#define SWZ128(o) ((o) ^ (((o) >> 3) & 0x70))

__device__ __forceinline__ void ldsm_x4(uint32_t* r, uint32_t addr) {
    asm volatile("ldmatrix.sync.aligned.m8n8.x4.shared.b16 {%0,%1,%2,%3}, [%4];"
                 : "=r"(r[0]), "=r"(r[1]), "=r"(r[2]), "=r"(r[3]) : "r"(addr));
}
__device__ __forceinline__ void mma_f16(float* c, const uint32_t* a,
                                        const uint32_t* b) {
    asm volatile("mma.sync.aligned.m16n8k16.row.col.f32.f16.f16.f32 "
                 "{%0,%1,%2,%3}, {%4,%5,%6,%7}, {%8,%9}, {%0,%1,%2,%3};"
                 : "+f"(c[0]), "+f"(c[1]), "+f"(c[2]), "+f"(c[3])
                 : "r"(a[0]), "r"(a[1]), "r"(a[2]), "r"(a[3]),
                   "r"(b[0]), "r"(b[1]));
}
__device__ __forceinline__ uint32_t fp16pack(float v0, float v1) {
    __half2 h = __floats2half2_rn(v0, v1);
    uint32_t r;
    *(__half2*)&r = h;
    return r;
}
__device__ __forceinline__ void cp_async16(uint32_t smem_dst, const void* gsrc) {
    asm volatile("cp.async.cg.shared.global [%0], [%1], 16;"
                 :: "r"(smem_dst), "l"(gsrc) : "memory");
}
__device__ __forceinline__ void cp_commit() {
    asm volatile("cp.async.commit_group;" ::: "memory");
}
__device__ __forceinline__ void cp_wait0() {
    asm volatile("cp.async.wait_group 0;" ::: "memory");
}

// ============================================================================
// Kernel 0: weight prep (fp16, pre-swizzled). CTAs 0..287: GEMM -> g_wb.
// CTAs 288..359: conv weights (27 oc padded to 32) -> g_wbc.
// ============================================================================
__global__ __launch_bounds__(256) void k0_prep(
    const float* __restrict__ wgt,
    const float* __restrict__ ow, const float* __restrict__ mw)
{
    const int blk = blockIdx.x;
    if (blk < 288) {
        int id = blk * 256 + threadIdx.x;  // 73728 items
        int ch = id >> 12;
        int r = id & 4095;
        int o = r >> 5, kp = r & 31;
        float2 wv = *(const float2*)(wgt + o * 1152 + ch * 64 + kp * 2);
        uint32_t off = SWZ128((uint32_t)(o * 128 + kp * 4));
        *(uint32_t*)(g_wb + ch * 16384 + off) = fp16pack(wv.x, wv.y);
    } else {
        int id = (blk - 288) * 256 + threadIdx.x;  // 18432 items
        int ch = id >> 10;
        int r = id & 1023;
        int oc = r >> 5, kp = r & 31;
        int k = ch * 64 + kp * 2;
        float v0 = 0.f, v1 = 0.f;
        if (oc < 18) {
            v0 = ow[oc * 1152 + k];
            v1 = ow[oc * 1152 + k + 1];
        } else if (oc < 27) {
            v0 = mw[(oc - 18) * 1152 + k];
            v1 = mw[(oc - 18) * 1152 + k + 1];
        }
        uint32_t off = SWZ128((uint32_t)(oc * 128 + kp * 4));
        *(uint32_t*)(g_wbc + ch * 4096 + off) = fp16pack(v0, v1);
    }
}

// ============================================================================
// Kernel 1: fused 27-channel conv (implicit GEMM, fp16) + bias + sigmoid +
// bilinear sampling metadata. grid = 256 (one (b,h) row, M=64), block = 256
// (8 warps, 4M x 2N, warp M16 x N16). Stage = A 8KB | B 4KB, double-buffered;
// conv sums land in smem, meta computed in epilogue (no global round-trip).
// ============================================================================
#define K1STG 12288
#define K1_CONV 24576                  // float[28][64] conv sums
#define K1_BYTES (K1_CONV + 28 * 64 * 4)

__device__ __forceinline__ void stage_Ac(
    char* buf, const float* __restrict__ xb, int h, int k0, int wid, int lane)
{
#pragma unroll
    for (int it = 0; it < 8; it++) {
        int c2 = it * 8 + wid;          // 0..63
        int kp = c2 >> 1;               // 0..31
        int m = (c2 & 1) * 32 + lane;   // 0..63
        int k = k0 + kp * 2;
        float v[2];
#pragma unroll
        for (int s2 = 0; s2 < 2; s2++) {
            int kk = k + s2;
            unsigned c = (unsigned)kk / 9u;
            int t = kk - c * 9;
            int ii = t / 3;
            int jj = t - ii * 3;
            int y = h + ii - 1;
            int xw = m + jj - 1;
            bool valid = ((unsigned)y < 64u) && ((unsigned)xw < 64u);
            v[s2] = valid ? xb[c * 4096 + y * 64 + xw] : 0.f;
        }
        uint32_t off = SWZ128((uint32_t)(m * 128 + kp * 4));
        *(uint32_t*)(buf + off) = fp16pack(v[0], v[1]);
    }
}

__global__ __launch_bounds__(256, 2) void k1_conv_meta(
    const float* __restrict__ x,
    const float* __restrict__ ob, const float* __restrict__ mb)
{
    extern __shared__ char sm[];
    const uint32_t sb = smem_u32(sm);
    const int tid = threadIdx.x;
    const int wid = tid >> 5, lid = tid & 31;
    const int bh = blockIdx.x;
    const int b = bh >> 6;
    const int h = bh & 63;
    const float* xb = x + b * CC * HH * WW;

    const int wM = (wid & 3) * 16;
    const int wN = (wid >> 2) * 16;
    const int a_row = lid & 15;
    const int a_col = (lid >> 4) * 8;
    const int b_row = (lid & 7) + ((lid >> 4) << 3);
    const int b_col = ((lid >> 3) & 1) * 8;

    float acc[2][4];
#pragma unroll
    for (int nt = 0; nt < 2; nt++)
#pragma unroll
        for (int i = 0; i < 4; i++) acc[nt][i] = 0.f;

    // prologue
    {
        cp_async16(sb + 8192 + tid * 16, g_wbc + tid * 16);
        cp_commit();
        stage_Ac(sm, xb, h, 0, wid, lid);
        cp_wait0();
    }
    __syncthreads();

    for (int ch = 0; ch < 18; ch++) {
        const int cur = ch & 1;
        const uint32_t baseA = sb + cur * K1STG;
        char* nxt = sm + (cur ^ 1) * K1STG;

        if (ch < 17) {
            cp_async16(sb + (cur ^ 1) * K1STG + 8192 + tid * 16,
                       g_wbc + (ch + 1) * 4096 + tid * 16);
            cp_commit();
        }

#pragma unroll
        for (int ks = 0; ks < 4; ks++) {
            uint32_t bhf[4];
            {
                uint32_t off = SWZ128((uint32_t)((wN + b_row) * 128 +
                                                 (ks * 16 + b_col) * 2));
                ldsm_x4(bhf, baseA + 8192 + off);
            }
            uint32_t ah[4];
            uint32_t off = SWZ128((uint32_t)((wM + a_row) * 128 +
                                             (ks * 16 + a_col) * 2));
            ldsm_x4(ah, baseA + off);
#pragma unroll
            for (int nt = 0; nt < 2; nt++)
                mma_f16(acc[nt], ah, &bhf[nt * 2]);
        }

        if (ch < 17) stage_Ac(nxt, xb, h, (ch + 1) * 64, wid, lid);
        cp_wait0();
        __syncthreads();
    }

    // conv sums -> smem
    float* cbuf = (float*)(sm + K1_CONV);
    const int g = lid >> 2, t2 = (lid & 3) * 2;
#pragma unroll
    for (int nt = 0; nt < 2; nt++) {
#pragma unroll
        for (int i = 0; i < 4; i++) {
            int n = wN + nt * 8 + t2 + (i & 1);
            if (n >= 27) continue;
            int m = wM + g + ((i >> 1) ? 8 : 0);
            cbuf[n * 64 + m] = acc[nt][i];
        }
    }
    __syncthreads();

    // meta epilogue (identical math to previous k1b)
    for (int i = tid; i < TT * 64; i += 256) {
        int t = i >> 6, ww = i & 63;
        float s0 = cbuf[(2 * t) * 64 + ww];
        float s1 = cbuf[(2 * t + 1) * 64 + ww];
        float s2 = cbuf[(18 + t) * 64 + ww];
        float offy = s0 + ob[2 * t];
        float offx = s1 + ob[2 * t + 1];
        float m = 1.f / (1.f + __expf(-(s2 + mb[t])));

        int ii = t / 3;
        int jj = t - ii * 3;
        float py = (float)(h - 1 + ii) + offy;
        float px = (float)(ww - 1 + jj) + offx;
        float fy = floorf(py), fx = floorf(px);
        float ly = py - fy, lx = px - fx;
        int y0 = (int)fy, x0 = (int)fx;
        float hy = 1.f - ly, hx = 1.f - lx;
        float w00 = hy * hx * m, w01 = hy * lx * m;
        float w10 = ly * hx * m, w11 = ly * lx * m;
        bool vy0 = (unsigned)y0 < 64u;
        bool vy1 = (unsigned)(y0 + 1) < 64u;
        bool vx0 = (unsigned)x0 < 64u;
        bool vx1 = (unsigned)(x0 + 1) < 64u;
        if (!(vy0 && vx0)) w00 = 0.f;
        if (!(vy0 && vx1)) w01 = 0.f;
        if (!(vy1 && vx0)) w10 = 0.f;
        if (!(vy1 && vx1)) w11 = 0.f;
        int y0a = min(max(y0, 0), 63), y1a = min(max(y0 + 1, 0), 63);
        int x0a = min(max(x0, 0), 63), x1a = min(max(x0 + 1, 0), 63);
        g_wt[bh * 576 + i] = make_float4(w00, w01, w10, w11);
        g_offp[bh * 576 + i] =
            make_ushort4((unsigned short)(y0a * 64 + x0a),
                         (unsigned short)(y0a * 64 + x1a),
                         (unsigned short)(y1a * 64 + x0a),
                         (unsigned short)(y1a * 64 + x1a));
    }
}

// ============================================================================
// Kernel 2: fused deformable sampling + fp16 mma.sync GEMM + BN + SiLU.
// grid = 256 rows, block = 256, 2 CTAs/SM. Stage = A 8KB | B 16KB = 24KB,
// double-buffered; gather software-pipelined across MMA blocks, warp-coherent.
// Epilogue: BN+SiLU -> stride-68 smem tile -> coalesced STG.128.
// ============================================================================
#define K2STG 24576
#define SM_WT  49152    // float4[576]
#define SM_OFF 58368    // ushort4[576]
#define SM_SC  62976    // float[128]
#define SM_SH  63488    // float[128]
#define SM2_BYTES 64000
#define EP_STRIDE 68    // floats per row in epilogue tile (16B-aligned, bank-safe)

__device__ __forceinline__ void issueA(
    float* pf, const float* __restrict__ xb,
    const ushort4* __restrict__ s_off, int k0, int grp, int wid, int lane)
{
#pragma unroll
    for (int j = 0; j < 2; j++) {
        int c2 = (grp * 2 + j) * 8 + wid;   // 0..63
        int kp = c2 >> 1;                   // 0..31
        int m = (c2 & 1) * 32 + lane;       // 0..63
        int k = k0 + kp * 2;
#pragma unroll
        for (int s2 = 0; s2 < 2; s2++) {
            int kk = k + s2;
            unsigned c = (unsigned)kk / 9u;
            int t = kk - c * 9;
            ushort4 o = s_off[t * 64 + m];
            const float* xp = xb + c * 4096;
            float* p = pf + (j * 2 + s2) * 4;
            p[0] = xp[o.x];
            p[1] = xp[o.y];
            p[2] = xp[o.z];
            p[3] = xp[o.w];
        }
    }
}

__device__ __forceinline__ void consumeA(
    char* buf, const float* pf,
    const float4* __restrict__ s_wt, int k0, int grp, int wid, int lane)
{
#pragma unroll
    for (int j = 0; j < 2; j++) {
        int c2 = (grp * 2 + j) * 8 + wid;
        int kp = c2 >> 1;
        int m = (c2 & 1) * 32 + lane;
        int k = k0 + kp * 2;
        float v[2];
#pragma unroll
        for (int s2 = 0; s2 < 2; s2++) {
            int kk = k + s2;
            unsigned c = (unsigned)kk / 9u;
            int t = kk - c * 9;
            float4 w = s_wt[t * 64 + m];
            const float* p = pf + (j * 2 + s2) * 4;
            v[s2] = w.x * p[0] + w.y * p[1] + w.z * p[2] + w.w * p[3];
        }
        uint32_t off = SWZ128((uint32_t)(m * 128 + kp * 4));
        *(uint32_t*)(buf + off) = fp16pack(v[0], v[1]);
    }
}

__global__ __launch_bounds__(256, 2) void k2_deform_mma(
    const float* __restrict__ x,
    const float* __restrict__ gamma, const float* __restrict__ beta,
    const float* __restrict__ mean, const float* __restrict__ var,
    float* __restrict__ out)
{
    extern __shared__ char sm[];
    const uint32_t sb = smem_u32(sm);
    const int tid = threadIdx.x;
    const int wid = tid >> 5, lid = tid & 31;
    const int blk = blockIdx.x;
    const int b = blk >> 6;
    const int h = blk & 63;

    float4* s_wt = (float4*)(sm + SM_WT);
    ushort4* s_off = (ushort4*)(sm + SM_OFF);
    float* s_sc = (float*)(sm + SM_SC);
    float* s_sh = (float*)(sm + SM_SH);

    const int mbase = (b * 64 + h) * 576;
    for (int i = tid; i < 576; i += 256) {
        s_wt[i] = g_wt[mbase + i];
        s_off[i] = g_offp[mbase + i];
    }
    if (tid < 128) {
        float sc = gamma[tid] * rsqrtf(var[tid] + 1e-5f);
        s_sc[tid] = sc;
        s_sh[tid] = beta[tid] - mean[tid] * sc;
    }
    const float* xb = x + b * CC * HH * WW;
    __syncthreads();

    const int wM = (wid & 1) * 32;
    const int wN = (wid >> 1) * 32;
    const int a_row = lid & 15;
    const int a_col = (lid >> 4) * 8;
    const int b_row = (lid & 7) + ((lid >> 4) << 3);
    const int b_col = ((lid >> 3) & 1) * 8;

    float acc[2][4][4];
#pragma unroll
    for (int mt = 0; mt < 2; mt++)
#pragma unroll
        for (int nt = 0; nt < 4; nt++)
#pragma unroll
            for (int i = 0; i < 4; i++) acc[mt][nt][i] = 0.f;

    float pf[16];

    // prologue: stage chunk 0 into buf 0
    {
        uint32_t bsm = sb + 8192;
#pragma unroll
        for (int it = 0; it < 4; it++) {
            int ln = it * 256 + tid;
            cp_async16(bsm + ln * 16, g_wb + ln * 16);
        }
        cp_commit();
#pragma unroll
        for (int g = 0; g < 4; g++) {
            issueA(pf, xb, s_off, 0, g, wid, lid);
            consumeA(sm, pf, s_wt, 0, g, wid, lid);
        }
        cp_wait0();
    }
    __syncthreads();

    for (int ch = 0; ch < 18; ch++) {
        const int cur = ch & 1;
        const uint32_t baseA = sb + cur * K2STG;
        char* nxt = sm + (cur ^ 1) * K2STG;
        const int kn = (ch + 1) * 64;
        const bool more = (ch < 17);

        if (more) {
            uint32_t bsm = sb + (cur ^ 1) * K2STG + 8192;
            const char* gsrc = g_wb + (ch + 1) * 16384;
#pragma unroll
            for (int it = 0; it < 4; it++) {
                int ln = it * 256 + tid;
                cp_async16(bsm + ln * 16, gsrc + ln * 16);
            }
            cp_commit();
            issueA(pf, xb, s_off, kn, 0, wid, lid);
        }

#pragma unroll
        for (int ks = 0; ks < 4; ks++) {
            uint32_t ah[2][4];
#pragma unroll
            for (int mt = 0; mt < 2; mt++) {
                uint32_t off = SWZ128((uint32_t)((wM + mt * 16 + a_row) * 128 +
                                                 (ks * 16 + a_col) * 2));
                ldsm_x4(ah[mt], baseA + off);
            }
            uint32_t bhf[2][4];
#pragma unroll
            for (int p = 0; p < 2; p++) {
                uint32_t off = SWZ128((uint32_t)((wN + p * 16 + b_row) * 128 +
                                                 (ks * 16 + b_col) * 2));
                ldsm_x4(bhf[p], baseA + 8192 + off);
            }
#pragma unroll
            for (int mt = 0; mt < 2; mt++)
#pragma unroll
                for (int nt = 0; nt < 4; nt++)
                    mma_f16(acc[mt][nt], ah[mt], &bhf[nt >> 1][(nt & 1) * 2]);

            if (more) {
                consumeA(nxt, pf, s_wt, kn, ks, wid, lid);
                if (ks < 3) issueA(pf, xb, s_off, kn, ks + 1, wid, lid);
            }
        }

        cp_wait0();
        __syncthreads();
    }

    // epilogue: BN + SiLU -> smem tile [128 n][64 m] (stride 68), then
    // coalesced row stores.
    float* obuf = (float*)sm;  // reuses stage region (34.8KB < 48KB)
    const int g = lid >> 2, t2 = (lid & 3) * 2;
#pragma unroll
    for (int mt = 0; mt < 2; mt++) {
#pragma unroll
        for (int nt = 0; nt < 4; nt++) {
#pragma unroll
            for (int i = 0; i < 4; i++) {
                int m = wM + mt * 16 + g + ((i >> 1) ? 8 : 0);
                int n = wN + nt * 8 + t2 + (i & 1);
                float v = acc[mt][nt][i] * s_sc[n] + s_sh[n];
                v = v / (1.f + __expf(-v));
                obuf[n * EP_STRIDE + m] = v;
            }
        }
    }
    __syncthreads();
    for (int i = tid; i < 2048; i += 256) {
        int n = i >> 4;
        int mq = (i & 15) * 4;
        float4 v4 = *(const float4*)(obuf + n * EP_STRIDE + mq);
        *(float4*)(out + ((b * OO + n) * HH + h) * WW + mq) = v4;
    }
}

extern "C" void kernel_launch(void* const* d_in, const int* in_sizes, int n_in,
                              void* d_out, int out_size)
{
    const float* x  = (const float*)d_in[0];
    const float* ow = (const float*)d_in[1];
    const float* ob = (const float*)d_in[2];
    const float* mw = (const float*)d_in[3];
    const float* mb = (const float*)d_in[4];
    const float* wg = (const float*)d_in[5];
    const float* gg = (const float*)d_in[6];
    const float* bt = (const float*)d_in[7];
    const float* mu = (const float*)d_in[8];
    const float* vr = (const float*)d_in[9];
    float* out = (float*)d_out;

    cudaFuncSetAttribute(k1_conv_meta,
                         cudaFuncAttributeMaxDynamicSharedMemorySize, K1_BYTES);
    cudaFuncSetAttribute(k2_deform_mma,
                         cudaFuncAttributeMaxDynamicSharedMemorySize, SM2_BYTES);

    k0_prep<<<360, 256>>>(wg, ow, mw);
    k1_conv_meta<<<BB * HH, 256, K1_BYTES>>>(x, ob, mb);
    k2_deform_mma<<<BB * HH, 256, SM2_BYTES>>>(x, gg, bt, mu, vr, out);
}

// round 15
// speedup vs baseline: 3.3971x; 1.0623x over previous
#include <cuda_runtime.h>
#include <cuda_fp16.h>
#include <cstdint>

// Problem constants (fixed by setup_inputs)
#define BB 4
#define CC 128
#define HH 64
#define WW 64
#define OO 128
#define TT 9

// Pre-converted, pre-swizzled fp16 GEMM weights: [18 chunks][16KB]
__device__ __align__(16) char g_wb[18 * 16384];
// Pre-converted, pre-swizzled fp16 conv weights (27 oc padded to 32): [18][4KB]
__device__ __align__(16) char g_wbc[18 * 4096];

// ---------------------------------------------------------------------------
// helpers
// ---------------------------------------------------------------------------
__device__ __forceinline__ uint32_t smem_u32(const void* p) {
    uint32_t a;
    asm("{ .reg .u64 t; cvta.to.shared.u64 t, %1; cvt.u32.u64 %0, t; }"
        : "=r"(a) : "l"(p));
    return a;
}
#define SWZ128(o) ((o) ^ (((o) >> 3) & 0x70))

__device__ __forceinline__ void ldsm_x4(uint32_t* r, uint32_t addr) {
    asm volatile("ldmatrix.sync.aligned.m8n8.x4.shared.b16 {%0,%1,%2,%3}, [%4];"
                 : "=r"(r[0]), "=r"(r[1]), "=r"(r[2]), "=r"(r[3]) : "r"(addr));
}
__device__ __forceinline__ void mma_f16(float* c, const uint32_t* a,
                                        const uint32_t* b) {
    asm volatile("mma.sync.aligned.m16n8k16.row.col.f32.f16.f16.f32 "
                 "{%0,%1,%2,%3}, {%4,%5,%6,%7}, {%8,%9}, {%0,%1,%2,%3};"
                 : "+f"(c[0]), "+f"(c[1]), "+f"(c[2]), "+f"(c[3])
                 : "r"(a[0]), "r"(a[1]), "r"(a[2]), "r"(a[3]),
                   "r"(b[0]), "r"(b[1]));
}
__device__ __forceinline__ uint32_t fp16pack(float v0, float v1) {
    __half2 h = __floats2half2_rn(v0, v1);
    uint32_t r;
    *(__half2*)&r = h;
    return r;
}
__device__ __forceinline__ void cp_async16(uint32_t smem_dst, const void* gsrc) {
    asm volatile("cp.async.cg.shared.global [%0], [%1], 16;"
                 :: "r"(smem_dst), "l"(gsrc) : "memory");
}
__device__ __forceinline__ void cp_commit() {
    asm volatile("cp.async.commit_group;" ::: "memory");
}
__device__ __forceinline__ void cp_wait0() {
    asm volatile("cp.async.wait_group 0;" ::: "memory");
}

// ============================================================================
// Kernel 0: weight prep (fp16, pre-swizzled). CTAs 0..287: GEMM -> g_wb.
// CTAs 288..359: conv weights (27 oc padded to 32) -> g_wbc.
// ============================================================================
__global__ __launch_bounds__(256) void k0_prep(
    const float* __restrict__ wgt,
    const float* __restrict__ ow, const float* __restrict__ mw)
{
    const int blk = blockIdx.x;
    if (blk < 288) {
        int id = blk * 256 + threadIdx.x;  // 73728 items
        int ch = id >> 12;
        int r = id & 4095;
        int o = r >> 5, kp = r & 31;
        float2 wv = *(const float2*)(wgt + o * 1152 + ch * 64 + kp * 2);
        uint32_t off = SWZ128((uint32_t)(o * 128 + kp * 4));
        *(uint32_t*)(g_wb + ch * 16384 + off) = fp16pack(wv.x, wv.y);
    } else {
        int id = (blk - 288) * 256 + threadIdx.x;  // 18432 items
        int ch = id >> 10;
        int r = id & 1023;
        int oc = r >> 5, kp = r & 31;
        int k = ch * 64 + kp * 2;
        float v0 = 0.f, v1 = 0.f;
        if (oc < 18) {
            v0 = ow[oc * 1152 + k];
            v1 = ow[oc * 1152 + k + 1];
        } else if (oc < 27) {
            v0 = mw[(oc - 18) * 1152 + k];
            v1 = mw[(oc - 18) * 1152 + k + 1];
        }
        uint32_t off = SWZ128((uint32_t)(oc * 128 + kp * 4));
        *(uint32_t*)(g_wbc + ch * 4096 + off) = fp16pack(v0, v1);
    }
}

// ============================================================================
// Fused kernel: per (b,h) row (grid 256, block 256, 2 CTAs/SM):
//   Phase A: 27-ch conv as fp16 implicit GEMM (M=64, N=32, K=1152, double
//            buffered 12KB stages) + bias + sigmoid + bilinear metadata,
//            written directly to smem (s_wt / s_off).
//   Phase B: deformable sampling (warp-coherent gather, software-pipelined
//            across MMA blocks) + fp16 GEMM (M=64, N=128) + BN + SiLU +
//            coalesced stores via smem transpose tile.
// smem layout (64000 B):
//   [0, 49152)      stage region (phase A: 2x12KB stages + 7KB conv buffer;
//                    phase B: 2x24KB stages; epilogue: 34.8KB out tile)
//   [49152, 58368)  s_wt  float4[576]
//   [58368, 62976)  s_off ushort4[576]
//   [62976, 63488)  s_sc, [63488, 64000) s_sh
// ============================================================================
#define K1STG 12288
#define K1_CONV 24576
#define K2STG 24576
#define SM_WT  49152
#define SM_OFF 58368
#define SM_SC  62976
#define SM_SH  63488
#define SMF_BYTES 64000
#define EP_STRIDE 68

__device__ __forceinline__ void stage_Ac(
    char* buf, const float* __restrict__ xb, int h, int k0, int wid, int lane)
{
#pragma unroll
    for (int it = 0; it < 8; it++) {
        int c2 = it * 8 + wid;          // 0..63
        int kp = c2 >> 1;               // 0..31
        int m = (c2 & 1) * 32 + lane;   // 0..63
        int k = k0 + kp * 2;
        float v[2];
#pragma unroll
        for (int s2 = 0; s2 < 2; s2++) {
            int kk = k + s2;
            unsigned c = (unsigned)kk / 9u;
            int t = kk - c * 9;
            int ii = t / 3;
            int jj = t - ii * 3;
            int y = h + ii - 1;
            int xw = m + jj - 1;
            bool valid = ((unsigned)y < 64u) && ((unsigned)xw < 64u);
            v[s2] = valid ? xb[c * 4096 + y * 64 + xw] : 0.f;
        }
        uint32_t off = SWZ128((uint32_t)(m * 128 + kp * 4));
        *(uint32_t*)(buf + off) = fp16pack(v[0], v[1]);
    }
}

__device__ __forceinline__ void issueA(
    float* pf, const float* __restrict__ xb,
    const ushort4* __restrict__ s_off, int k0, int grp, int wid, int lane)
{
#pragma unroll
    for (int j = 0; j < 2; j++) {
        int c2 = (grp * 2 + j) * 8 + wid;   // 0..63
        int kp = c2 >> 1;                   // 0..31
        int m = (c2 & 1) * 32 + lane;       // 0..63
        int k = k0 + kp * 2;
#pragma unroll
        for (int s2 = 0; s2 < 2; s2++) {
            int kk = k + s2;
            unsigned c = (unsigned)kk / 9u;
            int t = kk - c * 9;
            ushort4 o = s_off[t * 64 + m];
            const float* xp = xb + c * 4096;
            float* p = pf + (j * 2 + s2) * 4;
            p[0] = xp[o.x];
            p[1] = xp[o.y];
            p[2] = xp[o.z];
            p[3] = xp[o.w];
        }
    }
}

__device__ __forceinline__ void consumeA(
    char* buf, const float* pf,
    const float4* __restrict__ s_wt, int k0, int grp, int wid, int lane)
{
#pragma unroll
    for (int j = 0; j < 2; j++) {
        int c2 = (grp * 2 + j) * 8 + wid;
        int kp = c2 >> 1;
        int m = (c2 & 1) * 32 + lane;
        int k = k0 + kp * 2;
        float v[2];
#pragma unroll
        for (int s2 = 0; s2 < 2; s2++) {
            int kk = k + s2;
            unsigned c = (unsigned)kk / 9u;
            int t = kk - c * 9;
            float4 w = s_wt[t * 64 + m];
            const float* p = pf + (j * 2 + s2) * 4;
            v[s2] = w.x * p[0] + w.y * p[1] + w.z * p[2] + w.w * p[3];
        }
        uint32_t off = SWZ128((uint32_t)(m * 128 + kp * 4));
        *(uint32_t*)(buf + off) = fp16pack(v[0], v[1]);
    }
}

__global__ __launch_bounds__(256, 2) void k12_fused(
    const float* __restrict__ x,
    const float* __restrict__ ob, const float* __restrict__ mb,
    const float* __restrict__ gamma, const float* __restrict__ beta,
    const float* __restrict__ mean, const float* __restrict__ var,
    float* __restrict__ out)
{
    extern __shared__ char sm[];
    const uint32_t sb = smem_u32(sm);
    const int tid = threadIdx.x;
    const int wid = tid >> 5, lid = tid & 31;
    const int bh = blockIdx.x;
    const int b = bh >> 6;
    const int h = bh & 63;
    const float* xb = x + b * CC * HH * WW;

    float4* s_wt = (float4*)(sm + SM_WT);
    ushort4* s_off = (ushort4*)(sm + SM_OFF);
    float* s_sc = (float*)(sm + SM_SC);
    float* s_sh = (float*)(sm + SM_SH);

    if (tid < 128) {
        float sc = gamma[tid] * rsqrtf(var[tid] + 1e-5f);
        s_sc[tid] = sc;
        s_sh[tid] = beta[tid] - mean[tid] * sc;
    }

    // ============================ Phase A: conv + meta ============================
    {
        const int wM = (wid & 3) * 16;
        const int wN = (wid >> 2) * 16;
        const int a_row = lid & 15;
        const int a_col = (lid >> 4) * 8;
        const int b_row = (lid & 7) + ((lid >> 4) << 3);
        const int b_col = ((lid >> 3) & 1) * 8;

        float acc[2][4];
#pragma unroll
        for (int nt = 0; nt < 2; nt++)
#pragma unroll
            for (int i = 0; i < 4; i++) acc[nt][i] = 0.f;

        // prologue
        cp_async16(sb + 8192 + tid * 16, g_wbc + tid * 16);
        cp_commit();
        stage_Ac(sm, xb, h, 0, wid, lid);
        cp_wait0();
        __syncthreads();

        for (int ch = 0; ch < 18; ch++) {
            const int cur = ch & 1;
            const uint32_t baseA = sb + cur * K1STG;
            char* nxt = sm + (cur ^ 1) * K1STG;

            if (ch < 17) {
                cp_async16(sb + (cur ^ 1) * K1STG + 8192 + tid * 16,
                           g_wbc + (ch + 1) * 4096 + tid * 16);
                cp_commit();
            }

#pragma unroll
            for (int ks = 0; ks < 4; ks++) {
                uint32_t bhf[4];
                {
                    uint32_t off = SWZ128((uint32_t)((wN + b_row) * 128 +
                                                     (ks * 16 + b_col) * 2));
                    ldsm_x4(bhf, baseA + 8192 + off);
                }
                uint32_t ah[4];
                uint32_t off = SWZ128((uint32_t)((wM + a_row) * 128 +
                                                 (ks * 16 + a_col) * 2));
                ldsm_x4(ah, baseA + off);
#pragma unroll
                for (int nt = 0; nt < 2; nt++)
                    mma_f16(acc[nt], ah, &bhf[nt * 2]);
            }

            if (ch < 17) stage_Ac(nxt, xb, h, (ch + 1) * 64, wid, lid);
            cp_wait0();
            __syncthreads();
        }

        // conv sums -> smem
        float* cbuf = (float*)(sm + K1_CONV);
        const int g = lid >> 2, t2 = (lid & 3) * 2;
#pragma unroll
        for (int nt = 0; nt < 2; nt++) {
#pragma unroll
            for (int i = 0; i < 4; i++) {
                int n = wN + nt * 8 + t2 + (i & 1);
                if (n >= 27) continue;
                int m = wM + g + ((i >> 1) ? 8 : 0);
                cbuf[n * 64 + m] = acc[nt][i];
            }
        }
        __syncthreads();

        // meta epilogue -> smem s_wt / s_off
        for (int i = tid; i < TT * 64; i += 256) {
            int t = i >> 6, ww = i & 63;
            float s0 = cbuf[(2 * t) * 64 + ww];
            float s1 = cbuf[(2 * t + 1) * 64 + ww];
            float s2 = cbuf[(18 + t) * 64 + ww];
            float offy = s0 + ob[2 * t];
            float offx = s1 + ob[2 * t + 1];
            float m = 1.f / (1.f + __expf(-(s2 + mb[t])));

            int ii = t / 3;
            int jj = t - ii * 3;
            float py = (float)(h - 1 + ii) + offy;
            float px = (float)(ww - 1 + jj) + offx;
            float fy = floorf(py), fx = floorf(px);
            float ly = py - fy, lx = px - fx;
            int y0 = (int)fy, x0 = (int)fx;
            float hy = 1.f - ly, hx = 1.f - lx;
            float w00 = hy * hx * m, w01 = hy * lx * m;
            float w10 = ly * hx * m, w11 = ly * lx * m;
            bool vy0 = (unsigned)y0 < 64u;
            bool vy1 = (unsigned)(y0 + 1) < 64u;
            bool vx0 = (unsigned)x0 < 64u;
            bool vx1 = (unsigned)(x0 + 1) < 64u;
            if (!(vy0 && vx0)) w00 = 0.f;
            if (!(vy0 && vx1)) w01 = 0.f;
            if (!(vy1 && vx0)) w10 = 0.f;
            if (!(vy1 && vx1)) w11 = 0.f;
            int y0a = min(max(y0, 0), 63), y1a = min(max(y0 + 1, 0), 63);
            int x0a = min(max(x0, 0), 63), x1a = min(max(x0 + 1, 0), 63);
            s_wt[i] = make_float4(w00, w01, w10, w11);
            s_off[i] = make_ushort4((unsigned short)(y0a * 64 + x0a),
                                    (unsigned short)(y0a * 64 + x1a),
                                    (unsigned short)(y1a * 64 + x0a),
                                    (unsigned short)(y1a * 64 + x1a));
        }
    }
    __syncthreads();

    // ======================= Phase B: deformable GEMM =======================
    {
        const int wM = (wid & 1) * 32;
        const int wN = (wid >> 1) * 32;
        const int a_row = lid & 15;
        const int a_col = (lid >> 4) * 8;
        const int b_row = (lid & 7) + ((lid >> 4) << 3);
        const int b_col = ((lid >> 3) & 1) * 8;

        float acc[2][4][4];
#pragma unroll
        for (int mt = 0; mt < 2; mt++)
#pragma unroll
            for (int nt = 0; nt < 4; nt++)
#pragma unroll
                for (int i = 0; i < 4; i++) acc[mt][nt][i] = 0.f;

        float pf[16];

        // prologue: stage chunk 0 into buf 0
        {
            uint32_t bsm = sb + 8192;
#pragma unroll
            for (int it = 0; it < 4; it++) {
                int ln = it * 256 + tid;
                cp_async16(bsm + ln * 16, g_wb + ln * 16);
            }
            cp_commit();
#pragma unroll
            for (int g = 0; g < 4; g++) {
                issueA(pf, xb, s_off, 0, g, wid, lid);
                consumeA(sm, pf, s_wt, 0, g, wid, lid);
            }
            cp_wait0();
        }
        __syncthreads();

        for (int ch = 0; ch < 18; ch++) {
            const int cur = ch & 1;
            const uint32_t baseA = sb + cur * K2STG;
            char* nxt = sm + (cur ^ 1) * K2STG;
            const int kn = (ch + 1) * 64;
            const bool more = (ch < 17);

            if (more) {
                uint32_t bsm = sb + (cur ^ 1) * K2STG + 8192;
                const char* gsrc = g_wb + (ch + 1) * 16384;
#pragma unroll
                for (int it = 0; it < 4; it++) {
                    int ln = it * 256 + tid;
                    cp_async16(bsm + ln * 16, gsrc + ln * 16);
                }
                cp_commit();
                issueA(pf, xb, s_off, kn, 0, wid, lid);
            }

#pragma unroll
            for (int ks = 0; ks < 4; ks++) {
                uint32_t ah[2][4];
#pragma unroll
                for (int mt = 0; mt < 2; mt++) {
                    uint32_t off = SWZ128((uint32_t)((wM + mt * 16 + a_row) * 128 +
                                                     (ks * 16 + a_col) * 2));
                    ldsm_x4(ah[mt], baseA + off);
                }
                uint32_t bhf[2][4];
#pragma unroll
                for (int p = 0; p < 2; p++) {
                    uint32_t off = SWZ128((uint32_t)((wN + p * 16 + b_row) * 128 +
                                                     (ks * 16 + b_col) * 2));
                    ldsm_x4(bhf[p], baseA + 8192 + off);
                }
#pragma unroll
                for (int mt = 0; mt < 2; mt++)
#pragma unroll
                    for (int nt = 0; nt < 4; nt++)
                        mma_f16(acc[mt][nt], ah[mt], &bhf[nt >> 1][(nt & 1) * 2]);

                if (more) {
                    consumeA(nxt, pf, s_wt, kn, ks, wid, lid);
                    if (ks < 3) issueA(pf, xb, s_off, kn, ks + 1, wid, lid);
                }
            }

            cp_wait0();
            __syncthreads();
        }

        // epilogue: BN + SiLU -> smem tile -> coalesced stores
        float* obuf = (float*)sm;
        const int g = lid >> 2, t2 = (lid & 3) * 2;
#pragma unroll
        for (int mt = 0; mt < 2; mt++) {
#pragma unroll
            for (int nt = 0; nt < 4; nt++) {
#pragma unroll
                for (int i = 0; i < 4; i++) {
                    int m = wM + mt * 16 + g + ((i >> 1) ? 8 : 0);
                    int n = wN + nt * 8 + t2 + (i & 1);
                    float v = acc[mt][nt][i] * s_sc[n] + s_sh[n];
                    v = v / (1.f + __expf(-v));
                    obuf[n * EP_STRIDE + m] = v;
                }
            }
        }
        __syncthreads();
        for (int i = tid; i < 2048; i += 256) {
            int n = i >> 4;
            int mq = (i & 15) * 4;
            float4 v4 = *(const float4*)(obuf + n * EP_STRIDE + mq);
            *(float4*)(out + ((b * OO + n) * HH + h) * WW + mq) = v4;
        }
    }
}

extern "C" void kernel_launch(void* const* d_in, const int* in_sizes, int n_in,
                              void* d_out, int out_size)
{
    const float* x  = (const float*)d_in[0];
    const float* ow = (const float*)d_in[1];
    const float* ob = (const float*)d_in[2];
    const float* mw = (const float*)d_in[3];
    const float* mb = (const float*)d_in[4];
    const float* wg = (const float*)d_in[5];
    const float* gg = (const float*)d_in[6];
    const float* bt = (const float*)d_in[7];
    const float* mu = (const float*)d_in[8];
    const float* vr = (const float*)d_in[9];
    float* out = (float*)d_out;

    cudaFuncSetAttribute(k12_fused,
                         cudaFuncAttributeMaxDynamicSharedMemorySize, SMF_BYTES);

    k0_prep<<<360, 256>>>(wg, ow, mw);
    k12_fused<<<BB * HH, 256, SMF_BYTES>>>(x, ob, mb, gg, bt, mu, vr, out);
}